// round 1
// baseline (speedup 1.0000x reference)
#include <cuda_runtime.h>
#include <cuda_bf16.h>
#include <math.h>

#define BB   4
#define SS   512
#define HID_ 1024
#define HH   16
#define DD   64
#define NREL_ 64
#define TT   (BB*SS)      // 2048 tokens
#define BH   (BB*HH)      // 64

// ---------------- scratch (static device globals; no allocations) ----------
__device__ float g_Q[BH*SS*DD];                // 8 MB
__device__ float g_K[BH*SS*DD];                // 8 MB
__device__ float g_V[BH*SS*DD];                // 8 MB
__device__ float g_qrel[BH*SS*NREL_];          // 8 MB
__device__ float g_pr[BH*SS*NREL_];            // 8 MB
__device__ float g_probs[(size_t)BH*SS*SS];    // 64 MB
__device__ float g_attn[(size_t)TT*HID_];      // 8 MB

// ---------------- SGEMM: Y = X(M,K) @ W(N,K)^T + bias, M=2048 N=1024 K=1024 -
// mode 1: scatter output into (B,H,S,D) layout; mode 0: row-major (M,N).
__global__ void sgemm_nt_kernel(const float* __restrict__ X,
                                const float* __restrict__ W,
                                const float* __restrict__ bias,
                                float* __restrict__ out,
                                int mode)
{
    const int K = 1024, N = 1024;
    __shared__ float Xs[32][68];   // [BK][BM+pad], pad=4 keeps float4 alignment
    __shared__ float Ws[32][68];
    int tid = threadIdx.x;
    int tx = tid & 15, ty = tid >> 4;
    int row0 = blockIdx.y * 64;
    int col0 = blockIdx.x * 64;

    float acc[4][4] = {};

    for (int k0 = 0; k0 < K; k0 += 32) {
        #pragma unroll
        for (int p = 0; p < 8; p++) {
            int idx = tid + p * 256;          // 0..2047
            int c = idx & 31, r = idx >> 5;   // c: k within tile, r: row
            Xs[c][r] = X[(size_t)(row0 + r) * K + k0 + c];
            Ws[c][r] = W[(size_t)(col0 + r) * K + k0 + c];
        }
        __syncthreads();
        #pragma unroll
        for (int kk = 0; kk < 32; kk++) {
            float4 a4 = *(const float4*)&Xs[kk][ty * 4];
            float4 b4 = *(const float4*)&Ws[kk][tx * 4];
            float av[4] = {a4.x, a4.y, a4.z, a4.w};
            float bv[4] = {b4.x, b4.y, b4.z, b4.w};
            #pragma unroll
            for (int i = 0; i < 4; i++)
                #pragma unroll
                for (int j = 0; j < 4; j++)
                    acc[i][j] += av[i] * bv[j];
        }
        __syncthreads();
    }

    #pragma unroll
    for (int i = 0; i < 4; i++) {
        int m = row0 + ty * 4 + i;
        #pragma unroll
        for (int j = 0; j < 4; j++) {
            int n = col0 + tx * 4 + j;
            float y = acc[i][j] + bias[n];
            if (mode) {
                int b = m >> 9, s = m & 511, h = n >> 6, d = n & 63;
                out[(((size_t)b * HH + h) * SS + s) * DD + d] = y;
            } else {
                out[(size_t)m * N + n] = y;
            }
        }
    }
}

// ---------------- qrel = Q(BHS,64) @ rel_k_table(64,64)^T --------------------
__global__ void qrel_kernel(const float* __restrict__ relk)
{
    __shared__ float Qs[64][65];   // [d][row]
    __shared__ float Rs[64][65];   // [d][rel]
    int tid = threadIdx.x;
    int row0 = blockIdx.x * 64;

    #pragma unroll
    for (int p = 0; p < 16; p++) {
        int idx = tid + p * 256;       // 0..4095
        int d = idx & 63, r = idx >> 6;
        Qs[d][r] = g_Q[(size_t)(row0 + r) * 64 + d];
        Rs[d][r] = relk[r * 64 + d];
    }
    __syncthreads();

    int tx = tid & 15, ty = tid >> 4;
    float acc[4][4] = {};
    #pragma unroll
    for (int d = 0; d < 64; d++) {
        float a[4], b[4];
        #pragma unroll
        for (int i = 0; i < 4; i++) a[i] = Qs[d][ty * 4 + i];
        #pragma unroll
        for (int j = 0; j < 4; j++) b[j] = Rs[d][tx * 4 + j];
        #pragma unroll
        for (int i = 0; i < 4; i++)
            #pragma unroll
            for (int j = 0; j < 4; j++)
                acc[i][j] += a[i] * b[j];
    }
    #pragma unroll
    for (int i = 0; i < 4; i++)
        #pragma unroll
        for (int j = 0; j < 4; j++)
            g_qrel[(size_t)(row0 + ty * 4 + i) * NREL_ + tx * 4 + j] = acc[i][j];
}

// ---------------- block reductions ------------------------------------------
__device__ __forceinline__ float blockReduceMax(float v, float* red, int tid)
{
    #pragma unroll
    for (int o = 16; o; o >>= 1) v = fmaxf(v, __shfl_xor_sync(0xffffffffu, v, o));
    __syncthreads();
    if ((tid & 31) == 0) red[tid >> 5] = v;
    __syncthreads();
    float r = red[0];
    #pragma unroll
    for (int i = 1; i < 8; i++) r = fmaxf(r, red[i]);
    return r;
}
__device__ __forceinline__ float blockReduceSum(float v, float* red, int tid)
{
    #pragma unroll
    for (int o = 16; o; o >>= 1) v += __shfl_xor_sync(0xffffffffu, v, o);
    __syncthreads();
    if ((tid & 31) == 0) red[tid >> 5] = v;
    __syncthreads();
    float r = red[0];
    #pragma unroll
    for (int i = 1; i < 8; i++) r += red[i];
    return r;
}

// ---------------- fused scores + softmax + relation-bin accumulation --------
// grid (4 q-chunks, H, B), 256 threads. Dynamic smem holds full K tile (Kᵀ).
__global__ void attn_kernel(const int* __restrict__ mask)
{
    extern __shared__ float smf[];
    float* Kt   = smf;                   // 64 * 513
    float* qs   = Kt + 64 * 513;         // 4 * 64
    float* qrl  = qs + 4 * 64;           // 4 * 64
    float* bins = qrl + 4 * 64;          // 64
    float* red  = bins + 64;             // 8
    int*   idsm = (int*)(red + 8);       // 4 * 512

    int tid = threadIdx.x;
    int b = blockIdx.z, h = blockIdx.y, qc = blockIdx.x;
    int bh = b * HH + h;

    const float* Kbase = g_K + (size_t)bh * SS * DD;
    for (int idx = tid; idx < SS * DD; idx += 256) {
        int k = idx >> 6, d = idx & 63;
        Kt[d * 513 + k] = Kbase[idx];
    }
    __syncthreads();

    int q0 = qc * 128;
    for (int sg = 0; sg < 32; sg++) {
        int qb = q0 + sg * 4;
        {   // load 4 q rows + 4 qrel rows (256 threads = 4x64)
            int r = tid >> 6, d = tid & 63;
            qs[r * 64 + d]  = g_Q   [((size_t)bh * SS + qb + r) * DD   + d];
            qrl[r * 64 + d] = g_qrel[((size_t)bh * SS + qb + r) * NREL_ + d];
        }
        #pragma unroll
        for (int p = 0; p < 8; p++) {
            int idx = tid + p * 256;         // 0..2047
            int r = idx >> 9, j = idx & 511;
            idsm[idx] = mask[((size_t)b * SS + qb + r) * SS + j];
        }
        __syncthreads();

        // scores: each thread owns columns j0=tid, j1=tid+256 for 4 rows
        float acc[4][2] = {};
        int j0 = tid, j1 = tid + 256;
        #pragma unroll
        for (int d4 = 0; d4 < 16; d4++) {
            float qa[4][4];
            #pragma unroll
            for (int r = 0; r < 4; r++) {
                float4 qv = *(const float4*)&qs[r * 64 + d4 * 4];
                qa[r][0] = qv.x; qa[r][1] = qv.y; qa[r][2] = qv.z; qa[r][3] = qv.w;
            }
            #pragma unroll
            for (int dd = 0; dd < 4; dd++) {
                int d = d4 * 4 + dd;
                float k0 = Kt[d * 513 + j0];
                float k1 = Kt[d * 513 + j1];
                #pragma unroll
                for (int r = 0; r < 4; r++) {
                    acc[r][0] += qa[r][dd] * k0;
                    acc[r][1] += qa[r][dd] * k1;
                }
            }
        }

        // per-row softmax + relation bins
        #pragma unroll 1
        for (int r = 0; r < 4; r++) {
            int id0 = idsm[r * 512 + j0];
            int id1 = idsm[r * 512 + j1];
            // scores = (qk + qrel/4)/sqrt(64) + bias
            float s0 = acc[r][0] * 0.125f + qrl[r * 64 + id0] * 0.03125f
                     + (id0 > 0 ? 0.f : -10000.f);
            float s1 = acc[r][1] * 0.125f + qrl[r * 64 + id1] * 0.03125f
                     + (id1 > 0 ? 0.f : -10000.f);

            float mx  = blockReduceMax(fmaxf(s0, s1), red, tid);
            float e0 = __expf(s0 - mx), e1 = __expf(s1 - mx);
            float sum = blockReduceSum(e0 + e1, red, tid);
            float inv = 1.f / sum;
            float p0 = e0 * inv, p1 = e1 * inv;

            size_t prow = ((size_t)bh * SS + qb + r) * SS;
            g_probs[prow + j0] = p0;
            g_probs[prow + j1] = p1;

            if (tid < 64) bins[tid] = 0.f;
            __syncthreads();
            atomicAdd(&bins[id0], p0);
            atomicAdd(&bins[id1], p1);
            __syncthreads();
            if (tid < 64)
                g_pr[((size_t)bh * SS + qb + r) * NREL_ + tid] = bins[tid];
        }
        __syncthreads();
    }
}

// ---------------- out = probs @ V + 0.25 * pr @ rel_v_table ------------------
// grid (8 q-tiles, H, B), 256 threads, 64x64 output tile, 9 k-tiles.
__global__ void av_kernel(const float* __restrict__ relv)
{
    __shared__ float Ps[64][65];
    __shared__ float Vs[64][68];
    int tid = threadIdx.x;
    int tx = tid & 15, ty = tid >> 4;
    int b = blockIdx.z, h = blockIdx.y;
    int bh = b * HH + h;
    int q0 = blockIdx.x * 64;

    float acc[4][4] = {};

    for (int kt = 0; kt < 9; kt++) {
        #pragma unroll
        for (int p = 0; p < 16; p++) {
            int idx = tid + p * 256;        // 0..4095
            int c = idx & 63, r = idx >> 6;
            if (kt < 8) {
                Ps[r][c] = g_probs[((size_t)bh * SS + q0 + r) * SS + kt * 64 + c];
                Vs[r][c] = g_V   [((size_t)bh * SS + kt * 64 + r) * DD + c];
            } else {
                Ps[r][c] = 0.25f * g_pr[((size_t)bh * SS + q0 + r) * NREL_ + c];
                Vs[r][c] = relv[r * 64 + c];
            }
        }
        __syncthreads();
        #pragma unroll
        for (int kk = 0; kk < 64; kk++) {
            float4 b4 = *(const float4*)&Vs[kk][tx * 4];
            float bv[4] = {b4.x, b4.y, b4.z, b4.w};
            float av[4];
            #pragma unroll
            for (int i = 0; i < 4; i++) av[i] = Ps[ty * 4 + i][kk];
            #pragma unroll
            for (int i = 0; i < 4; i++)
                #pragma unroll
                for (int j = 0; j < 4; j++)
                    acc[i][j] += av[i] * bv[j];
        }
        __syncthreads();
    }

    #pragma unroll
    for (int i = 0; i < 4; i++) {
        int q = q0 + ty * 4 + i;
        #pragma unroll
        for (int j = 0; j < 4; j++) {
            int d = tx * 4 + j;
            g_attn[((size_t)b * SS + q) * HID_ + h * DD + d] = acc[i][j];
        }
    }
}

// ---------------- launch -----------------------------------------------------
extern "C" void kernel_launch(void* const* d_in, const int* in_sizes, int n_in,
                              void* d_out, int out_size)
{
    const float* q_in = (const float*)d_in[0];
    const float* k_in = (const float*)d_in[1];
    const float* v_in = (const float*)d_in[2];
    const int*   mask = (const int*)  d_in[3];
    const float* Wq   = (const float*)d_in[4];
    const float* bq   = (const float*)d_in[5];
    const float* Wk   = (const float*)d_in[6];
    const float* bk   = (const float*)d_in[7];
    const float* Wv   = (const float*)d_in[8];
    const float* bv   = (const float*)d_in[9];
    const float* Wo   = (const float*)d_in[10];
    const float* bo   = (const float*)d_in[11];
    const float* relk = (const float*)d_in[12];
    const float* relv = (const float*)d_in[13];
    float* out = (float*)d_out;

    float *pQ, *pK, *pV, *pAttn;
    cudaGetSymbolAddress((void**)&pQ,    g_Q);
    cudaGetSymbolAddress((void**)&pK,    g_K);
    cudaGetSymbolAddress((void**)&pV,    g_V);
    cudaGetSymbolAddress((void**)&pAttn, g_attn);

    dim3 gg(HID_ / 64, TT / 64);   // (16, 32)
    sgemm_nt_kernel<<<gg, 256>>>(q_in, Wq, bq, pQ, 1);
    sgemm_nt_kernel<<<gg, 256>>>(k_in, Wk, bk, pK, 1);
    sgemm_nt_kernel<<<gg, 256>>>(v_in, Wv, bv, pV, 1);

    qrel_kernel<<<BH * SS / 64, 256>>>(relk);

    const int smemA = (64 * 513 + 4 * 64 + 4 * 64 + 64 + 8) * 4 + 4 * 512 * 4;
    cudaFuncSetAttribute(attn_kernel,
                         cudaFuncAttributeMaxDynamicSharedMemorySize, smemA);
    attn_kernel<<<dim3(4, HH, BB), 256, smemA>>>(mask);

    av_kernel<<<dim3(SS / 64, HH, BB), 256>>>(relv);

    sgemm_nt_kernel<<<gg, 256>>>(pAttn, Wo, bo, out, 0);
}

// round 2
// speedup vs baseline: 1.3908x; 1.3908x over previous
#include <cuda_runtime.h>
#include <cuda_bf16.h>
#include <math.h>
#include <stdint.h>

#define BB   4
#define SS   512
#define HID_ 1024
#define HH   16
#define DD   64
#define NREL_ 64
#define TT   (BB*SS)      // 2048 tokens
#define BH   (BB*HH)      // 64

// ---------------- scratch (static device globals; no allocations) ----------
__device__ float g_Q[BH*SS*DD];                // 8 MB
__device__ float g_K[BH*SS*DD];                // 8 MB
__device__ float g_V[BH*SS*DD];                // 8 MB
__device__ float g_qrel[BH*SS*NREL_];          // 8 MB
__device__ float g_pr[BH*SS*NREL_];            // 8 MB
__device__ float g_probs[(size_t)BH*SS*SS];    // 64 MB
__device__ float g_attn[(size_t)TT*HID_];      // 8 MB

// ======================= tf32 tensor-core GEMM =============================
// Y(M=2048, N=1024) = X(M,K=1024) @ W(N,K)^T + bias
// scatter=1: write into (B,H,S,D); scatter=0: row-major (M,N).
struct GemmArgs {
    const float* X[3];
    const float* W[3];
    const float* b[3];
    float*       O[3];
    int scatter;
};

__device__ __forceinline__ uint32_t f2tf32(float x) {
    uint32_t r;
    asm("cvt.rna.tf32.f32 %0, %1;" : "=r"(r) : "f"(x));
    return r;
}

__device__ __forceinline__ void mma_tf32(float c[4], const uint32_t a[4],
                                         const uint32_t b2[2]) {
    asm volatile(
        "mma.sync.aligned.m16n8k8.row.col.f32.tf32.tf32.f32 "
        "{%0,%1,%2,%3}, {%4,%5,%6,%7}, {%8,%9}, {%0,%1,%2,%3};"
        : "+f"(c[0]), "+f"(c[1]), "+f"(c[2]), "+f"(c[3])
        : "r"(a[0]), "r"(a[1]), "r"(a[2]), "r"(a[3]),
          "r"(b2[0]), "r"(b2[1]));
}

#define GBM 128
#define GBN 128
#define GBK 32
#define GLDW 36   // smem row stride (words): conflict-free fragment loads

__global__ void __launch_bounds__(256, 2)
tf32_gemm_kernel(GemmArgs args)
{
    const int K = 1024, N = 1024;
    int mat = blockIdx.z;
    const float* __restrict__ X    = args.X[mat];
    const float* __restrict__ W    = args.W[mat];
    const float* __restrict__ bias = args.b[mat];
    float* __restrict__ O          = args.O[mat];

    __shared__ uint32_t Xs[GBM][GLDW];
    __shared__ uint32_t Ws[GBN][GLDW];

    int tid  = threadIdx.x;
    int lane = tid & 31;
    int wid  = tid >> 5;
    int wm   = wid & 1;        // 2 warps over M
    int wn   = wid >> 1;       // 4 warps over N
    int gid  = lane >> 2;      // 0..7
    int tig  = lane & 3;       // 0..3

    int row0 = blockIdx.y * GBM;
    int col0 = blockIdx.x * GBN;

    // loader indices: each thread: 4 rows {lr, lr+32, lr+64, lr+96}, 4 cols
    int lr = tid >> 3;            // 0..31
    int lc = (tid & 7) * 4;       // 0..28

    float acc[4][4][4] = {};      // [mt][nt][c0..c3]

    for (int k0 = 0; k0 < K; k0 += GBK) {
        #pragma unroll
        for (int p = 0; p < 4; p++) {
            int r = lr + p * 32;
            float4 xv = *(const float4*)&X[(size_t)(row0 + r) * K + k0 + lc];
            float4 wv = *(const float4*)&W[(size_t)(col0 + r) * K + k0 + lc];
            uint4 xt = make_uint4(f2tf32(xv.x), f2tf32(xv.y), f2tf32(xv.z), f2tf32(xv.w));
            uint4 wt = make_uint4(f2tf32(wv.x), f2tf32(wv.y), f2tf32(wv.z), f2tf32(wv.w));
            *(uint4*)&Xs[r][lc] = xt;
            *(uint4*)&Ws[r][lc] = wt;
        }
        __syncthreads();

        #pragma unroll
        for (int ks = 0; ks < 4; ks++) {
            int kb = ks * 8;
            uint32_t af[4][4];
            #pragma unroll
            for (int mt = 0; mt < 4; mt++) {
                int m = wm * 64 + mt * 16;
                af[mt][0] = Xs[m + gid    ][kb + tig    ];
                af[mt][1] = Xs[m + gid + 8][kb + tig    ];
                af[mt][2] = Xs[m + gid    ][kb + tig + 4];
                af[mt][3] = Xs[m + gid + 8][kb + tig + 4];
            }
            uint32_t bf[4][2];
            #pragma unroll
            for (int nt = 0; nt < 4; nt++) {
                int n = wn * 32 + nt * 8;
                bf[nt][0] = Ws[n + gid][kb + tig    ];
                bf[nt][1] = Ws[n + gid][kb + tig + 4];
            }
            #pragma unroll
            for (int mt = 0; mt < 4; mt++)
                #pragma unroll
                for (int nt = 0; nt < 4; nt++)
                    mma_tf32(acc[mt][nt], af[mt], bf[nt]);
        }
        __syncthreads();
    }

    // epilogue
    #pragma unroll
    for (int mt = 0; mt < 4; mt++) {
        #pragma unroll
        for (int nt = 0; nt < 4; nt++) {
            #pragma unroll
            for (int c = 0; c < 4; c++) {
                int m = row0 + wm * 64 + mt * 16 + gid + (c >= 2 ? 8 : 0);
                int n = col0 + wn * 32 + nt * 8 + tig * 2 + (c & 1);
                float y = acc[mt][nt][c] + bias[n];
                if (args.scatter) {
                    int b = m >> 9, s = m & 511, h = n >> 6, d = n & 63;
                    O[(((size_t)b * HH + h) * SS + s) * DD + d] = y;
                } else {
                    O[(size_t)m * N + n] = y;
                }
            }
        }
    }
}

// ---------------- qrel = Q(BHS,64) @ rel_k_table(64,64)^T --------------------
__global__ void qrel_kernel(const float* __restrict__ relk)
{
    __shared__ float Qs[64][65];   // [d][row]
    __shared__ float Rs[64][65];   // [d][rel]
    int tid = threadIdx.x;
    int row0 = blockIdx.x * 64;

    #pragma unroll
    for (int p = 0; p < 16; p++) {
        int idx = tid + p * 256;       // 0..4095
        int d = idx & 63, r = idx >> 6;
        Qs[d][r] = g_Q[(size_t)(row0 + r) * 64 + d];
        Rs[d][r] = relk[r * 64 + d];
    }
    __syncthreads();

    int tx = tid & 15, ty = tid >> 4;
    float acc[4][4] = {};
    #pragma unroll
    for (int d = 0; d < 64; d++) {
        float a[4], b[4];
        #pragma unroll
        for (int i = 0; i < 4; i++) a[i] = Qs[d][ty * 4 + i];
        #pragma unroll
        for (int j = 0; j < 4; j++) b[j] = Rs[d][tx * 4 + j];
        #pragma unroll
        for (int i = 0; i < 4; i++)
            #pragma unroll
            for (int j = 0; j < 4; j++)
                acc[i][j] += a[i] * b[j];
    }
    #pragma unroll
    for (int i = 0; i < 4; i++)
        #pragma unroll
        for (int j = 0; j < 4; j++)
            g_qrel[(size_t)(row0 + ty * 4 + i) * NREL_ + tx * 4 + j] = acc[i][j];
}

// ---------------- block reductions ------------------------------------------
__device__ __forceinline__ float blockReduceMax(float v, float* red, int tid)
{
    #pragma unroll
    for (int o = 16; o; o >>= 1) v = fmaxf(v, __shfl_xor_sync(0xffffffffu, v, o));
    __syncthreads();
    if ((tid & 31) == 0) red[tid >> 5] = v;
    __syncthreads();
    float r = red[0];
    #pragma unroll
    for (int i = 1; i < 8; i++) r = fmaxf(r, red[i]);
    return r;
}
__device__ __forceinline__ float blockReduceSum(float v, float* red, int tid)
{
    #pragma unroll
    for (int o = 16; o; o >>= 1) v += __shfl_xor_sync(0xffffffffu, v, o);
    __syncthreads();
    if ((tid & 31) == 0) red[tid >> 5] = v;
    __syncthreads();
    float r = red[0];
    #pragma unroll
    for (int i = 1; i < 8; i++) r += red[i];
    return r;
}

// ---------------- fused scores + softmax + relation-bin accumulation --------
// grid (4 q-chunks, H, B), 256 threads. Dynamic smem holds full K tile (Kᵀ).
__global__ void attn_kernel(const int* __restrict__ mask)
{
    extern __shared__ float smf[];
    float* Kt   = smf;                   // 64 * 513
    float* qs   = Kt + 64 * 513;         // 4 * 64
    float* qrl  = qs + 4 * 64;           // 4 * 64
    float* bins = qrl + 4 * 64;          // 64
    float* red  = bins + 64;             // 8
    int*   idsm = (int*)(red + 8);       // 4 * 512

    int tid = threadIdx.x;
    int b = blockIdx.z, h = blockIdx.y, qc = blockIdx.x;
    int bh = b * HH + h;

    const float* Kbase = g_K + (size_t)bh * SS * DD;
    for (int idx = tid; idx < SS * DD; idx += 256) {
        int k = idx >> 6, d = idx & 63;
        Kt[d * 513 + k] = Kbase[idx];
    }
    __syncthreads();

    int q0 = qc * 128;
    for (int sg = 0; sg < 32; sg++) {
        int qb = q0 + sg * 4;
        {   // load 4 q rows + 4 qrel rows (256 threads = 4x64)
            int r = tid >> 6, d = tid & 63;
            qs[r * 64 + d]  = g_Q   [((size_t)bh * SS + qb + r) * DD   + d];
            qrl[r * 64 + d] = g_qrel[((size_t)bh * SS + qb + r) * NREL_ + d];
        }
        #pragma unroll
        for (int p = 0; p < 8; p++) {
            int idx = tid + p * 256;         // 0..2047
            int r = idx >> 9, j = idx & 511;
            idsm[idx] = mask[((size_t)b * SS + qb + r) * SS + j];
        }
        __syncthreads();

        // scores: each thread owns columns j0=tid, j1=tid+256 for 4 rows
        float acc[4][2] = {};
        int j0 = tid, j1 = tid + 256;
        #pragma unroll
        for (int d4 = 0; d4 < 16; d4++) {
            float qa[4][4];
            #pragma unroll
            for (int r = 0; r < 4; r++) {
                float4 qv = *(const float4*)&qs[r * 64 + d4 * 4];
                qa[r][0] = qv.x; qa[r][1] = qv.y; qa[r][2] = qv.z; qa[r][3] = qv.w;
            }
            #pragma unroll
            for (int dd = 0; dd < 4; dd++) {
                int d = d4 * 4 + dd;
                float k0 = Kt[d * 513 + j0];
                float k1 = Kt[d * 513 + j1];
                #pragma unroll
                for (int r = 0; r < 4; r++) {
                    acc[r][0] += qa[r][dd] * k0;
                    acc[r][1] += qa[r][dd] * k1;
                }
            }
        }

        // per-row softmax + relation bins
        #pragma unroll 1
        for (int r = 0; r < 4; r++) {
            int id0 = idsm[r * 512 + j0];
            int id1 = idsm[r * 512 + j1];
            // scores = (qk + qrel/4)/sqrt(64) + bias
            float s0 = acc[r][0] * 0.125f + qrl[r * 64 + id0] * 0.03125f
                     + (id0 > 0 ? 0.f : -10000.f);
            float s1 = acc[r][1] * 0.125f + qrl[r * 64 + id1] * 0.03125f
                     + (id1 > 0 ? 0.f : -10000.f);

            float mx  = blockReduceMax(fmaxf(s0, s1), red, tid);
            float e0 = __expf(s0 - mx), e1 = __expf(s1 - mx);
            float sum = blockReduceSum(e0 + e1, red, tid);
            float inv = 1.f / sum;
            float p0 = e0 * inv, p1 = e1 * inv;

            size_t prow = ((size_t)bh * SS + qb + r) * SS;
            g_probs[prow + j0] = p0;
            g_probs[prow + j1] = p1;

            if (tid < 64) bins[tid] = 0.f;
            __syncthreads();
            atomicAdd(&bins[id0], p0);
            atomicAdd(&bins[id1], p1);
            __syncthreads();
            if (tid < 64)
                g_pr[((size_t)bh * SS + qb + r) * NREL_ + tid] = bins[tid];
        }
        __syncthreads();
    }
}

// ---------------- out = probs @ V + 0.25 * pr @ rel_v_table ------------------
// grid (8 q-tiles, H, B), 256 threads, 64x64 output tile, 9 k-tiles.
__global__ void av_kernel(const float* __restrict__ relv)
{
    __shared__ float Ps[64][65];
    __shared__ float Vs[64][68];
    int tid = threadIdx.x;
    int tx = tid & 15, ty = tid >> 4;
    int b = blockIdx.z, h = blockIdx.y;
    int bh = b * HH + h;
    int q0 = blockIdx.x * 64;

    float acc[4][4] = {};

    for (int kt = 0; kt < 9; kt++) {
        #pragma unroll
        for (int p = 0; p < 16; p++) {
            int idx = tid + p * 256;        // 0..4095
            int c = idx & 63, r = idx >> 6;
            if (kt < 8) {
                Ps[r][c] = g_probs[((size_t)bh * SS + q0 + r) * SS + kt * 64 + c];
                Vs[r][c] = g_V   [((size_t)bh * SS + kt * 64 + r) * DD + c];
            } else {
                Ps[r][c] = 0.25f * g_pr[((size_t)bh * SS + q0 + r) * NREL_ + c];
                Vs[r][c] = relv[r * 64 + c];
            }
        }
        __syncthreads();
        #pragma unroll
        for (int kk = 0; kk < 64; kk++) {
            float4 b4 = *(const float4*)&Vs[kk][tx * 4];
            float bv[4] = {b4.x, b4.y, b4.z, b4.w};
            float av[4];
            #pragma unroll
            for (int i = 0; i < 4; i++) av[i] = Ps[ty * 4 + i][kk];
            #pragma unroll
            for (int i = 0; i < 4; i++)
                #pragma unroll
                for (int j = 0; j < 4; j++)
                    acc[i][j] += av[i] * bv[j];
        }
        __syncthreads();
    }

    #pragma unroll
    for (int i = 0; i < 4; i++) {
        int q = q0 + ty * 4 + i;
        #pragma unroll
        for (int j = 0; j < 4; j++) {
            int d = tx * 4 + j;
            g_attn[((size_t)b * SS + q) * HID_ + h * DD + d] = acc[i][j];
        }
    }
}

// ---------------- launch -----------------------------------------------------
extern "C" void kernel_launch(void* const* d_in, const int* in_sizes, int n_in,
                              void* d_out, int out_size)
{
    const float* q_in = (const float*)d_in[0];
    const float* k_in = (const float*)d_in[1];
    const float* v_in = (const float*)d_in[2];
    const int*   mask = (const int*)  d_in[3];
    const float* Wq   = (const float*)d_in[4];
    const float* bq   = (const float*)d_in[5];
    const float* Wk   = (const float*)d_in[6];
    const float* bk   = (const float*)d_in[7];
    const float* Wv   = (const float*)d_in[8];
    const float* bv   = (const float*)d_in[9];
    const float* Wo   = (const float*)d_in[10];
    const float* bo   = (const float*)d_in[11];
    const float* relk = (const float*)d_in[12];
    const float* relv = (const float*)d_in[13];
    float* out = (float*)d_out;

    float *pQ, *pK, *pV, *pAttn;
    cudaGetSymbolAddress((void**)&pQ,    g_Q);
    cudaGetSymbolAddress((void**)&pK,    g_K);
    cudaGetSymbolAddress((void**)&pV,    g_V);
    cudaGetSymbolAddress((void**)&pAttn, g_attn);

    // fused QKV projection (tensor core, tf32)
    GemmArgs qkv;
    qkv.X[0] = q_in; qkv.X[1] = k_in; qkv.X[2] = v_in;
    qkv.W[0] = Wq;   qkv.W[1] = Wk;   qkv.W[2] = Wv;
    qkv.b[0] = bq;   qkv.b[1] = bk;   qkv.b[2] = bv;
    qkv.O[0] = pQ;   qkv.O[1] = pK;   qkv.O[2] = pV;
    qkv.scatter = 1;
    tf32_gemm_kernel<<<dim3(HID_ / GBN, TT / GBM, 3), 256>>>(qkv);

    qrel_kernel<<<BH * SS / 64, 256>>>(relk);

    const int smemA = (64 * 513 + 4 * 64 + 4 * 64 + 64 + 8) * 4 + 4 * 512 * 4;
    cudaFuncSetAttribute(attn_kernel,
                         cudaFuncAttributeMaxDynamicSharedMemorySize, smemA);
    attn_kernel<<<dim3(4, HH, BB), 256, smemA>>>(mask);

    av_kernel<<<dim3(SS / 64, HH, BB), 256>>>(relv);

    // output projection (tensor core, tf32)
    GemmArgs og;
    og.X[0] = pAttn; og.W[0] = Wo; og.b[0] = bo; og.O[0] = out;
    og.X[1] = og.X[2] = nullptr; og.W[1] = og.W[2] = nullptr;
    og.b[1] = og.b[2] = nullptr; og.O[1] = og.O[2] = nullptr;
    og.scatter = 0;
    tf32_gemm_kernel<<<dim3(HID_ / GBN, TT / GBM, 1), 256>>>(og);
}

// round 3
// speedup vs baseline: 1.7138x; 1.2322x over previous
#include <cuda_runtime.h>
#include <cuda_bf16.h>
#include <math.h>
#include <stdint.h>

#define BB   4
#define SS   512
#define HID_ 1024
#define HH   16
#define DD   64
#define NREL_ 64
#define TT   (BB*SS)      // 2048 tokens
#define BH   (BB*HH)      // 64

// ---------------- scratch (static device globals; no allocations) ----------
__device__ float g_Q[BH*SS*DD];                // 8 MB
__device__ float g_K[BH*SS*DD];                // 8 MB
__device__ float g_V[BH*SS*DD];                // 8 MB
__device__ float g_qrel[BH*SS*NREL_];          // 8 MB
__device__ float g_pr[BH*SS*NREL_];            // 8 MB
__device__ float g_probs[(size_t)BH*SS*SS];    // 64 MB
__device__ float g_attn[(size_t)TT*HID_];      // 8 MB
// tf32-rounded copies of GEMM inputs
__device__ float g_rq[TT*HID_];                // 8 MB
__device__ float g_rk[TT*HID_];                // 8 MB
__device__ float g_rv[TT*HID_];                // 8 MB
__device__ float g_wq[HID_*HID_];              // 4 MB
__device__ float g_wk[HID_*HID_];              // 4 MB
__device__ float g_wv[HID_*HID_];              // 4 MB
__device__ float g_wo[HID_*HID_];              // 4 MB

__device__ __forceinline__ uint32_t f2tf32(float x) {
    uint32_t r;
    asm("cvt.rna.tf32.f32 %0, %1;" : "=r"(r) : "f"(x));
    return r;
}

// ---------------- tf32 pre-rounding pass ------------------------------------
struct RoundArgs {
    const float4* src[7];
    float4*       dst[7];
    int           n4[7];
};
__global__ void round_tf32_kernel(RoundArgs a)
{
    int seg = blockIdx.y;
    const float4* s = a.src[seg];
    float4*       d = a.dst[seg];
    int n = a.n4[seg];
    for (int i = blockIdx.x * blockDim.x + threadIdx.x; i < n;
         i += gridDim.x * blockDim.x) {
        float4 v = s[i];
        float4 o;
        o.x = __uint_as_float(f2tf32(v.x));
        o.y = __uint_as_float(f2tf32(v.y));
        o.z = __uint_as_float(f2tf32(v.z));
        o.w = __uint_as_float(f2tf32(v.w));
        d[i] = o;
    }
}

// ======================= tf32 tensor-core GEMM (pipelined) ==================
// Y(M=2048, N=1024) = X(M,K=1024) @ W(N,K)^T + bias
// X,W must already be tf32-rounded fp32. scatter=1: (B,H,S,D); 0: row-major.
struct GemmArgs {
    const float* X[3];
    const float* W[3];
    const float* b[3];
    float*       O[3];
    int scatter;
};

__device__ __forceinline__ void mma_tf32(float c[4], const uint32_t a[4],
                                         const uint32_t b2[2]) {
    asm volatile(
        "mma.sync.aligned.m16n8k8.row.col.f32.tf32.tf32.f32 "
        "{%0,%1,%2,%3}, {%4,%5,%6,%7}, {%8,%9}, {%0,%1,%2,%3};"
        : "+f"(c[0]), "+f"(c[1]), "+f"(c[2]), "+f"(c[3])
        : "r"(a[0]), "r"(a[1]), "r"(a[2]), "r"(a[3]),
          "r"(b2[0]), "r"(b2[1]));
}

__device__ __forceinline__ void cp_async16(uint32_t smem, const void* g) {
    asm volatile("cp.async.cg.shared.global [%0], [%1], 16;\n"
                 :: "r"(smem), "l"(g));
}

#define GBM 128
#define GBN 128
#define GBK 32
#define GLDW 36                       // smem row stride (words), conflict-free
#define GTILE (GBM * GLDW)            // words per matrix per stage

__global__ void __launch_bounds__(256, 2)
tf32_gemm_kernel(GemmArgs args)
{
    const int K = 1024, N = 1024;
    int mat = blockIdx.z;
    const float* __restrict__ X    = args.X[mat];
    const float* __restrict__ W    = args.W[mat];
    const float* __restrict__ bias = args.b[mat];
    float* __restrict__ O          = args.O[mat];

    extern __shared__ uint32_t smg[];   // [2 stages][2 mats][128][36]

    int tid  = threadIdx.x;
    int lane = tid & 31;
    int wid  = tid >> 5;
    int wm   = wid & 1;        // 2 warps over M (64 rows each)
    int wn   = wid >> 1;       // 4 warps over N (32 cols each)
    int gid  = lane >> 2;      // 0..7
    int tig  = lane & 3;       // 0..3

    int row0 = blockIdx.y * GBM;
    int col0 = blockIdx.x * GBN;

    int lr = tid >> 3;            // 0..31
    int lc = (tid & 7) * 4;       // 0,4,..,28

    uint32_t smem_base;
    {
        uint64_t t = __cvta_generic_to_shared(smg);
        smem_base = (uint32_t)t;
    }

    float acc[4][4][4] = {};      // [mt][nt][c]

    const int KT = K / GBK;       // 32

    // issue async copy of k-tile kt into stage st
    auto issue = [&](int st, int k0) {
        uint32_t xs = smem_base + (st * 2 * GTILE) * 4;
        uint32_t ws = xs + GTILE * 4;
        #pragma unroll
        for (int p = 0; p < 4; p++) {
            int r = lr + p * 32;
            cp_async16(xs + (r * GLDW + lc) * 4,
                       &X[(size_t)(row0 + r) * K + k0 + lc]);
            cp_async16(ws + (r * GLDW + lc) * 4,
                       &W[(size_t)(col0 + r) * K + k0 + lc]);
        }
    };

    issue(0, 0);
    asm volatile("cp.async.commit_group;\n" ::);

    for (int kt = 0; kt < KT; kt++) {
        if (kt + 1 < KT) {
            issue((kt + 1) & 1, (kt + 1) * GBK);
            asm volatile("cp.async.commit_group;\n" ::);
            asm volatile("cp.async.wait_group 1;\n" ::);
        } else {
            asm volatile("cp.async.wait_group 0;\n" ::);
        }
        __syncthreads();

        const uint32_t* Xs = smg + ((kt & 1) * 2) * GTILE;
        const uint32_t* Ws = Xs + GTILE;

        #pragma unroll
        for (int ks = 0; ks < 4; ks++) {
            int kb = ks * 8;
            uint32_t af[4][4];
            #pragma unroll
            for (int mt = 0; mt < 4; mt++) {
                int m = wm * 64 + mt * 16;
                af[mt][0] = Xs[(m + gid    ) * GLDW + kb + tig    ];
                af[mt][1] = Xs[(m + gid + 8) * GLDW + kb + tig    ];
                af[mt][2] = Xs[(m + gid    ) * GLDW + kb + tig + 4];
                af[mt][3] = Xs[(m + gid + 8) * GLDW + kb + tig + 4];
            }
            uint32_t bf[4][2];
            #pragma unroll
            for (int nt = 0; nt < 4; nt++) {
                int n = wn * 32 + nt * 8;
                bf[nt][0] = Ws[(n + gid) * GLDW + kb + tig    ];
                bf[nt][1] = Ws[(n + gid) * GLDW + kb + tig + 4];
            }
            #pragma unroll
            for (int mt = 0; mt < 4; mt++)
                #pragma unroll
                for (int nt = 0; nt < 4; nt++)
                    mma_tf32(acc[mt][nt], af[mt], bf[nt]);
        }
        __syncthreads();
    }

    // epilogue
    #pragma unroll
    for (int mt = 0; mt < 4; mt++) {
        #pragma unroll
        for (int nt = 0; nt < 4; nt++) {
            #pragma unroll
            for (int c = 0; c < 4; c++) {
                int m = row0 + wm * 64 + mt * 16 + gid + (c >= 2 ? 8 : 0);
                int n = col0 + wn * 32 + nt * 8 + tig * 2 + (c & 1);
                float y = acc[mt][nt][c] + bias[n];
                if (args.scatter) {
                    int b = m >> 9, s = m & 511, h = n >> 6, d = n & 63;
                    O[(((size_t)b * HH + h) * SS + s) * DD + d] = y;
                } else {
                    O[(size_t)m * N + n] = y;
                }
            }
        }
    }
}

// ---------------- qrel = Q(BHS,64) @ rel_k_table(64,64)^T --------------------
__global__ void qrel_kernel(const float* __restrict__ relk)
{
    __shared__ float Qs[64][65];
    __shared__ float Rs[64][65];
    int tid = threadIdx.x;
    int row0 = blockIdx.x * 64;

    #pragma unroll
    for (int p = 0; p < 16; p++) {
        int idx = tid + p * 256;
        int d = idx & 63, r = idx >> 6;
        Qs[d][r] = g_Q[(size_t)(row0 + r) * 64 + d];
        Rs[d][r] = relk[r * 64 + d];
    }
    __syncthreads();

    int tx = tid & 15, ty = tid >> 4;
    float acc[4][4] = {};
    #pragma unroll
    for (int d = 0; d < 64; d++) {
        float a[4], b[4];
        #pragma unroll
        for (int i = 0; i < 4; i++) a[i] = Qs[d][ty * 4 + i];
        #pragma unroll
        for (int j = 0; j < 4; j++) b[j] = Rs[d][tx * 4 + j];
        #pragma unroll
        for (int i = 0; i < 4; i++)
            #pragma unroll
            for (int j = 0; j < 4; j++)
                acc[i][j] += a[i] * b[j];
    }
    #pragma unroll
    for (int i = 0; i < 4; i++)
        #pragma unroll
        for (int j = 0; j < 4; j++)
            g_qrel[(size_t)(row0 + ty * 4 + i) * NREL_ + tx * 4 + j] = acc[i][j];
}

// ---------------- block reductions ------------------------------------------
__device__ __forceinline__ float blockReduceMax(float v, float* red, int tid)
{
    #pragma unroll
    for (int o = 16; o; o >>= 1) v = fmaxf(v, __shfl_xor_sync(0xffffffffu, v, o));
    __syncthreads();
    if ((tid & 31) == 0) red[tid >> 5] = v;
    __syncthreads();
    float r = red[0];
    #pragma unroll
    for (int i = 1; i < 8; i++) r = fmaxf(r, red[i]);
    return r;
}
__device__ __forceinline__ float blockReduceSum(float v, float* red, int tid)
{
    #pragma unroll
    for (int o = 16; o; o >>= 1) v += __shfl_xor_sync(0xffffffffu, v, o);
    __syncthreads();
    if ((tid & 31) == 0) red[tid >> 5] = v;
    __syncthreads();
    float r = red[0];
    #pragma unroll
    for (int i = 1; i < 8; i++) r += red[i];
    return r;
}

// ---------------- fused scores + softmax + relation-bin accumulation --------
__global__ void attn_kernel(const int* __restrict__ mask)
{
    extern __shared__ float smf[];
    float* Kt   = smf;                   // 64 * 513
    float* qs   = Kt + 64 * 513;         // 4 * 64
    float* qrl  = qs + 4 * 64;           // 4 * 64
    float* bins = qrl + 4 * 64;          // 64
    float* red  = bins + 64;             // 8
    int*   idsm = (int*)(red + 8);       // 4 * 512

    int tid = threadIdx.x;
    int b = blockIdx.z, h = blockIdx.y, qc = blockIdx.x;
    int bh = b * HH + h;

    const float* Kbase = g_K + (size_t)bh * SS * DD;
    for (int idx = tid; idx < SS * DD; idx += 256) {
        int k = idx >> 6, d = idx & 63;
        Kt[d * 513 + k] = Kbase[idx];
    }
    __syncthreads();

    int q0 = qc * 128;
    for (int sg = 0; sg < 32; sg++) {
        int qb = q0 + sg * 4;
        {
            int r = tid >> 6, d = tid & 63;
            qs[r * 64 + d]  = g_Q   [((size_t)bh * SS + qb + r) * DD   + d];
            qrl[r * 64 + d] = g_qrel[((size_t)bh * SS + qb + r) * NREL_ + d];
        }
        #pragma unroll
        for (int p = 0; p < 8; p++) {
            int idx = tid + p * 256;
            int r = idx >> 9, j = idx & 511;
            idsm[idx] = mask[((size_t)b * SS + qb + r) * SS + j];
        }
        __syncthreads();

        float acc[4][2] = {};
        int j0 = tid, j1 = tid + 256;
        #pragma unroll
        for (int d4 = 0; d4 < 16; d4++) {
            float qa[4][4];
            #pragma unroll
            for (int r = 0; r < 4; r++) {
                float4 qv = *(const float4*)&qs[r * 64 + d4 * 4];
                qa[r][0] = qv.x; qa[r][1] = qv.y; qa[r][2] = qv.z; qa[r][3] = qv.w;
            }
            #pragma unroll
            for (int dd = 0; dd < 4; dd++) {
                int d = d4 * 4 + dd;
                float k0 = Kt[d * 513 + j0];
                float k1 = Kt[d * 513 + j1];
                #pragma unroll
                for (int r = 0; r < 4; r++) {
                    acc[r][0] += qa[r][dd] * k0;
                    acc[r][1] += qa[r][dd] * k1;
                }
            }
        }

        #pragma unroll 1
        for (int r = 0; r < 4; r++) {
            int id0 = idsm[r * 512 + j0];
            int id1 = idsm[r * 512 + j1];
            float s0 = acc[r][0] * 0.125f + qrl[r * 64 + id0] * 0.03125f
                     + (id0 > 0 ? 0.f : -10000.f);
            float s1 = acc[r][1] * 0.125f + qrl[r * 64 + id1] * 0.03125f
                     + (id1 > 0 ? 0.f : -10000.f);

            float mx  = blockReduceMax(fmaxf(s0, s1), red, tid);
            float e0 = __expf(s0 - mx), e1 = __expf(s1 - mx);
            float sum = blockReduceSum(e0 + e1, red, tid);
            float inv = 1.f / sum;
            float p0 = e0 * inv, p1 = e1 * inv;

            size_t prow = ((size_t)bh * SS + qb + r) * SS;
            g_probs[prow + j0] = p0;
            g_probs[prow + j1] = p1;

            if (tid < 64) bins[tid] = 0.f;
            __syncthreads();
            atomicAdd(&bins[id0], p0);
            atomicAdd(&bins[id1], p1);
            __syncthreads();
            if (tid < 64)
                g_pr[((size_t)bh * SS + qb + r) * NREL_ + tid] = bins[tid];
        }
        __syncthreads();
    }
}

// ---------------- out = probs @ V + 0.25 * pr @ rel_v_table ------------------
__global__ void av_kernel(const float* __restrict__ relv)
{
    __shared__ float Ps[64][65];
    __shared__ float Vs[64][68];
    int tid = threadIdx.x;
    int tx = tid & 15, ty = tid >> 4;
    int b = blockIdx.z, h = blockIdx.y;
    int bh = b * HH + h;
    int q0 = blockIdx.x * 64;

    float acc[4][4] = {};

    for (int kt = 0; kt < 9; kt++) {
        #pragma unroll
        for (int p = 0; p < 16; p++) {
            int idx = tid + p * 256;
            int c = idx & 63, r = idx >> 6;
            if (kt < 8) {
                Ps[r][c] = g_probs[((size_t)bh * SS + q0 + r) * SS + kt * 64 + c];
                Vs[r][c] = g_V   [((size_t)bh * SS + kt * 64 + r) * DD + c];
            } else {
                Ps[r][c] = 0.25f * g_pr[((size_t)bh * SS + q0 + r) * NREL_ + c];
                Vs[r][c] = relv[r * 64 + c];
            }
        }
        __syncthreads();
        #pragma unroll
        for (int kk = 0; kk < 64; kk++) {
            float4 b4 = *(const float4*)&Vs[kk][tx * 4];
            float bv[4] = {b4.x, b4.y, b4.z, b4.w};
            float av[4];
            #pragma unroll
            for (int i = 0; i < 4; i++) av[i] = Ps[ty * 4 + i][kk];
            #pragma unroll
            for (int i = 0; i < 4; i++)
                #pragma unroll
                for (int j = 0; j < 4; j++)
                    acc[i][j] += av[i] * bv[j];
        }
        __syncthreads();
    }

    // store tf32-rounded fp32 so the output projection can cp.async directly
    #pragma unroll
    for (int i = 0; i < 4; i++) {
        int q = q0 + ty * 4 + i;
        #pragma unroll
        for (int j = 0; j < 4; j++) {
            int d = tx * 4 + j;
            g_attn[((size_t)b * SS + q) * HID_ + h * DD + d] =
                __uint_as_float(f2tf32(acc[i][j]));
        }
    }
}

// ---------------- launch -----------------------------------------------------
extern "C" void kernel_launch(void* const* d_in, const int* in_sizes, int n_in,
                              void* d_out, int out_size)
{
    const float* q_in = (const float*)d_in[0];
    const float* k_in = (const float*)d_in[1];
    const float* v_in = (const float*)d_in[2];
    const int*   mask = (const int*)  d_in[3];
    const float* Wq   = (const float*)d_in[4];
    const float* bq   = (const float*)d_in[5];
    const float* Wk   = (const float*)d_in[6];
    const float* bk   = (const float*)d_in[7];
    const float* Wv   = (const float*)d_in[8];
    const float* bv   = (const float*)d_in[9];
    const float* Wo   = (const float*)d_in[10];
    const float* bo   = (const float*)d_in[11];
    const float* relk = (const float*)d_in[12];
    const float* relv = (const float*)d_in[13];
    float* out = (float*)d_out;

    float *pQ, *pK, *pV, *pAttn;
    float *pRq, *pRk, *pRv, *pWq, *pWk, *pWv, *pWo;
    cudaGetSymbolAddress((void**)&pQ,    g_Q);
    cudaGetSymbolAddress((void**)&pK,    g_K);
    cudaGetSymbolAddress((void**)&pV,    g_V);
    cudaGetSymbolAddress((void**)&pAttn, g_attn);
    cudaGetSymbolAddress((void**)&pRq,   g_rq);
    cudaGetSymbolAddress((void**)&pRk,   g_rk);
    cudaGetSymbolAddress((void**)&pRv,   g_rv);
    cudaGetSymbolAddress((void**)&pWq,   g_wq);
    cudaGetSymbolAddress((void**)&pWk,   g_wk);
    cudaGetSymbolAddress((void**)&pWv,   g_wv);
    cudaGetSymbolAddress((void**)&pWo,   g_wo);

    // 1) tf32 pre-rounding of all GEMM inputs
    RoundArgs ra;
    ra.src[0] = (const float4*)q_in; ra.dst[0] = (float4*)pRq; ra.n4[0] = TT*HID_/4;
    ra.src[1] = (const float4*)k_in; ra.dst[1] = (float4*)pRk; ra.n4[1] = TT*HID_/4;
    ra.src[2] = (const float4*)v_in; ra.dst[2] = (float4*)pRv; ra.n4[2] = TT*HID_/4;
    ra.src[3] = (const float4*)Wq;   ra.dst[3] = (float4*)pWq; ra.n4[3] = HID_*HID_/4;
    ra.src[4] = (const float4*)Wk;   ra.dst[4] = (float4*)pWk; ra.n4[4] = HID_*HID_/4;
    ra.src[5] = (const float4*)Wv;   ra.dst[5] = (float4*)pWv; ra.n4[5] = HID_*HID_/4;
    ra.src[6] = (const float4*)Wo;   ra.dst[6] = (float4*)pWo; ra.n4[6] = HID_*HID_/4;
    round_tf32_kernel<<<dim3(512, 7), 256>>>(ra);

    const int gemmSmem = 2 * 2 * GTILE * 4;   // 73728 B
    cudaFuncSetAttribute(tf32_gemm_kernel,
                         cudaFuncAttributeMaxDynamicSharedMemorySize, gemmSmem);

    // 2) fused QKV projection
    GemmArgs qkv;
    qkv.X[0] = pRq; qkv.X[1] = pRk; qkv.X[2] = pRv;
    qkv.W[0] = pWq; qkv.W[1] = pWk; qkv.W[2] = pWv;
    qkv.b[0] = bq;  qkv.b[1] = bk;  qkv.b[2] = bv;
    qkv.O[0] = pQ;  qkv.O[1] = pK;  qkv.O[2] = pV;
    qkv.scatter = 1;
    tf32_gemm_kernel<<<dim3(HID_ / GBN, TT / GBM, 3), 256, gemmSmem>>>(qkv);

    qrel_kernel<<<BH * SS / 64, 256>>>(relk);

    const int smemA = (64 * 513 + 4 * 64 + 4 * 64 + 64 + 8) * 4 + 4 * 512 * 4;
    cudaFuncSetAttribute(attn_kernel,
                         cudaFuncAttributeMaxDynamicSharedMemorySize, smemA);
    attn_kernel<<<dim3(4, HH, BB), 256, smemA>>>(mask);

    av_kernel<<<dim3(SS / 64, HH, BB), 256>>>(relv);

    // 3) output projection
    GemmArgs og;
    og.X[0] = pAttn; og.W[0] = pWo; og.b[0] = bo; og.O[0] = out;
    og.X[1] = og.X[2] = nullptr; og.W[1] = og.W[2] = nullptr;
    og.b[1] = og.b[2] = nullptr; og.O[1] = og.O[2] = nullptr;
    og.scatter = 0;
    tf32_gemm_kernel<<<dim3(HID_ / GBN, TT / GBM, 1), 256, gemmSmem>>>(og);
}

// round 4
// speedup vs baseline: 2.2721x; 1.3257x over previous
#include <cuda_runtime.h>
#include <cuda_bf16.h>
#include <math.h>
#include <stdint.h>

#define BB   4
#define SS   512
#define HID_ 1024
#define HH   16
#define DD   64
#define NREL_ 64
#define TT   (BB*SS)      // 2048 tokens
#define BH   (BB*HH)      // 64

// ---------------- scratch (static device globals; no allocations) ----------
__device__ float g_Q[BH*SS*DD];                // 8 MB
__device__ float g_K[BH*SS*DD];                // 8 MB
__device__ float g_V[BH*SS*DD];                // 8 MB
__device__ float g_qrel[BH*SS*NREL_];          // 8 MB
__device__ float g_pr[BH*SS*NREL_];            // 8 MB
__device__ float g_probs[(size_t)BH*SS*SS];    // 64 MB (scores -> probs in place)
__device__ float g_attn[(size_t)TT*HID_];      // 8 MB
// tf32-rounded copies of GEMM inputs
__device__ float g_rq[TT*HID_];                // 8 MB
__device__ float g_rk[TT*HID_];                // 8 MB
__device__ float g_rv[TT*HID_];                // 8 MB
__device__ float g_wq[HID_*HID_];              // 4 MB
__device__ float g_wk[HID_*HID_];              // 4 MB
__device__ float g_wv[HID_*HID_];              // 4 MB
__device__ float g_wo[HID_*HID_];              // 4 MB

__device__ __forceinline__ uint32_t f2tf32(float x) {
    uint32_t r;
    asm("cvt.rna.tf32.f32 %0, %1;" : "=r"(r) : "f"(x));
    return r;
}

// ---------------- tf32 pre-rounding pass ------------------------------------
struct RoundArgs {
    const float4* src[7];
    float4*       dst[7];
    int           n4[7];
};
__global__ void round_tf32_kernel(RoundArgs a)
{
    int seg = blockIdx.y;
    const float4* s = a.src[seg];
    float4*       d = a.dst[seg];
    int n = a.n4[seg];
    for (int i = blockIdx.x * blockDim.x + threadIdx.x; i < n;
         i += gridDim.x * blockDim.x) {
        float4 v = s[i];
        float4 o;
        o.x = __uint_as_float(f2tf32(v.x));
        o.y = __uint_as_float(f2tf32(v.y));
        o.z = __uint_as_float(f2tf32(v.z));
        o.w = __uint_as_float(f2tf32(v.w));
        d[i] = o;
    }
}

// ======================= tf32 tensor-core GEMM (pipelined) ==================
struct GemmArgs {
    const float* X[3];
    const float* W[3];
    const float* b[3];
    float*       O[3];
    int scatter;
};

__device__ __forceinline__ void mma_tf32(float c[4], const uint32_t a[4],
                                         const uint32_t b2[2]) {
    asm volatile(
        "mma.sync.aligned.m16n8k8.row.col.f32.tf32.tf32.f32 "
        "{%0,%1,%2,%3}, {%4,%5,%6,%7}, {%8,%9}, {%0,%1,%2,%3};"
        : "+f"(c[0]), "+f"(c[1]), "+f"(c[2]), "+f"(c[3])
        : "r"(a[0]), "r"(a[1]), "r"(a[2]), "r"(a[3]),
          "r"(b2[0]), "r"(b2[1]));
}

__device__ __forceinline__ void cp_async16(uint32_t smem, const void* g) {
    asm volatile("cp.async.cg.shared.global [%0], [%1], 16;\n"
                 :: "r"(smem), "l"(g));
}

#define GBM 128
#define GBN 128
#define GBK 32
#define GLDW 36
#define GTILE (GBM * GLDW)

__global__ void __launch_bounds__(256, 2)
tf32_gemm_kernel(GemmArgs args)
{
    const int K = 1024, N = 1024;
    int mat = blockIdx.z;
    const float* __restrict__ X    = args.X[mat];
    const float* __restrict__ W    = args.W[mat];
    const float* __restrict__ bias = args.b[mat];
    float* __restrict__ O          = args.O[mat];

    extern __shared__ uint32_t smg[];

    int tid  = threadIdx.x;
    int lane = tid & 31;
    int wid  = tid >> 5;
    int wm   = wid & 1;
    int wn   = wid >> 1;
    int gid  = lane >> 2;
    int tig  = lane & 3;

    int row0 = blockIdx.y * GBM;
    int col0 = blockIdx.x * GBN;

    int lr = tid >> 3;
    int lc = (tid & 7) * 4;

    uint32_t smem_base;
    {
        uint64_t t = __cvta_generic_to_shared(smg);
        smem_base = (uint32_t)t;
    }

    float acc[4][4][4] = {};
    const int KT = K / GBK;

    auto issue = [&](int st, int k0) {
        uint32_t xs = smem_base + (st * 2 * GTILE) * 4;
        uint32_t ws = xs + GTILE * 4;
        #pragma unroll
        for (int p = 0; p < 4; p++) {
            int r = lr + p * 32;
            cp_async16(xs + (r * GLDW + lc) * 4,
                       &X[(size_t)(row0 + r) * K + k0 + lc]);
            cp_async16(ws + (r * GLDW + lc) * 4,
                       &W[(size_t)(col0 + r) * K + k0 + lc]);
        }
    };

    issue(0, 0);
    asm volatile("cp.async.commit_group;\n" ::);

    for (int kt = 0; kt < KT; kt++) {
        if (kt + 1 < KT) {
            issue((kt + 1) & 1, (kt + 1) * GBK);
            asm volatile("cp.async.commit_group;\n" ::);
            asm volatile("cp.async.wait_group 1;\n" ::);
        } else {
            asm volatile("cp.async.wait_group 0;\n" ::);
        }
        __syncthreads();

        const uint32_t* Xs = smg + ((kt & 1) * 2) * GTILE;
        const uint32_t* Ws = Xs + GTILE;

        #pragma unroll
        for (int ks = 0; ks < 4; ks++) {
            int kb = ks * 8;
            uint32_t af[4][4];
            #pragma unroll
            for (int mt = 0; mt < 4; mt++) {
                int m = wm * 64 + mt * 16;
                af[mt][0] = Xs[(m + gid    ) * GLDW + kb + tig    ];
                af[mt][1] = Xs[(m + gid + 8) * GLDW + kb + tig    ];
                af[mt][2] = Xs[(m + gid    ) * GLDW + kb + tig + 4];
                af[mt][3] = Xs[(m + gid + 8) * GLDW + kb + tig + 4];
            }
            uint32_t bf[4][2];
            #pragma unroll
            for (int nt = 0; nt < 4; nt++) {
                int n = wn * 32 + nt * 8;
                bf[nt][0] = Ws[(n + gid) * GLDW + kb + tig    ];
                bf[nt][1] = Ws[(n + gid) * GLDW + kb + tig + 4];
            }
            #pragma unroll
            for (int mt = 0; mt < 4; mt++)
                #pragma unroll
                for (int nt = 0; nt < 4; nt++)
                    mma_tf32(acc[mt][nt], af[mt], bf[nt]);
        }
        __syncthreads();
    }

    #pragma unroll
    for (int mt = 0; mt < 4; mt++) {
        #pragma unroll
        for (int nt = 0; nt < 4; nt++) {
            #pragma unroll
            for (int c = 0; c < 4; c++) {
                int m = row0 + wm * 64 + mt * 16 + gid + (c >= 2 ? 8 : 0);
                int n = col0 + wn * 32 + nt * 8 + tig * 2 + (c & 1);
                float y = acc[mt][nt][c] + bias[n];
                if (args.scatter) {
                    int b = m >> 9, s = m & 511, h = n >> 6, d = n & 63;
                    O[(((size_t)b * HH + h) * SS + s) * DD + d] = y;
                } else {
                    O[(size_t)m * N + n] = y;
                }
            }
        }
    }
}

// ================= qk_scores: scores = Q @ K^T per (b,h), tf32 MMA ==========
// grid (4 ntiles, 4 mtiles, 64 bh), 256 threads, 128x128 tile, K=64.
#define QKW 68   // smem row stride (words)

__global__ void __launch_bounds__(256, 2)
qk_scores_kernel()
{
    extern __shared__ uint32_t sm2[];   // Qs[128][68] + Ks[128][68]
    uint32_t* Qs = sm2;
    uint32_t* Ks = sm2 + 128 * QKW;

    int tid  = threadIdx.x;
    int lane = tid & 31;
    int wid  = tid >> 5;
    int wm   = wid & 1;
    int wn   = wid >> 1;
    int gid  = lane >> 2;
    int tig  = lane & 3;

    int bh   = blockIdx.z;
    int row0 = blockIdx.y * 128;
    int col0 = blockIdx.x * 128;

    const float* Qg = g_Q + (size_t)bh * SS * DD;
    const float* Kg = g_K + (size_t)bh * SS * DD;

    // load + tf32-round: each thread 32 elems (8 float4) of Q and K
    int lrow = tid >> 1;
    int lcol = (tid & 1) * 32;
    #pragma unroll
    for (int p = 0; p < 8; p++) {
        int c = lcol + p * 4;
        float4 qv = *(const float4*)&Qg[(size_t)(row0 + lrow) * DD + c];
        float4 kv = *(const float4*)&Kg[(size_t)(col0 + lrow) * DD + c];
        Qs[lrow * QKW + c + 0] = f2tf32(qv.x);
        Qs[lrow * QKW + c + 1] = f2tf32(qv.y);
        Qs[lrow * QKW + c + 2] = f2tf32(qv.z);
        Qs[lrow * QKW + c + 3] = f2tf32(qv.w);
        Ks[lrow * QKW + c + 0] = f2tf32(kv.x);
        Ks[lrow * QKW + c + 1] = f2tf32(kv.y);
        Ks[lrow * QKW + c + 2] = f2tf32(kv.z);
        Ks[lrow * QKW + c + 3] = f2tf32(kv.w);
    }
    __syncthreads();

    float acc[4][4][4] = {};
    #pragma unroll
    for (int ks = 0; ks < 8; ks++) {
        int kb = ks * 8;
        uint32_t af[4][4];
        #pragma unroll
        for (int mt = 0; mt < 4; mt++) {
            int m = wm * 64 + mt * 16;
            af[mt][0] = Qs[(m + gid    ) * QKW + kb + tig    ];
            af[mt][1] = Qs[(m + gid + 8) * QKW + kb + tig    ];
            af[mt][2] = Qs[(m + gid    ) * QKW + kb + tig + 4];
            af[mt][3] = Qs[(m + gid + 8) * QKW + kb + tig + 4];
        }
        uint32_t bf[4][2];
        #pragma unroll
        for (int nt = 0; nt < 4; nt++) {
            int n = wn * 32 + nt * 8;
            bf[nt][0] = Ks[(n + gid) * QKW + kb + tig    ];
            bf[nt][1] = Ks[(n + gid) * QKW + kb + tig + 4];
        }
        #pragma unroll
        for (int mt = 0; mt < 4; mt++)
            #pragma unroll
            for (int nt = 0; nt < 4; nt++)
                mma_tf32(acc[mt][nt], af[mt], bf[nt]);
    }

    // store raw scores (float2 per c-pair; each 8-lane octet = one 32B sector)
    float* Og = g_probs + (size_t)bh * SS * SS;
    #pragma unroll
    for (int mt = 0; mt < 4; mt++) {
        #pragma unroll
        for (int nt = 0; nt < 4; nt++) {
            int m0 = row0 + wm * 64 + mt * 16 + gid;
            int n  = col0 + wn * 32 + nt * 8 + tig * 2;
            *(float2*)&Og[(size_t)m0 * SS + n] =
                make_float2(acc[mt][nt][0], acc[mt][nt][1]);
            *(float2*)&Og[(size_t)(m0 + 8) * SS + n] =
                make_float2(acc[mt][nt][2], acc[mt][nt][3]);
        }
    }
}

// ================= softmax: warp per row, no block barriers ==================
// scores (in g_probs) -> probs (in place) + relation bins (g_pr)
__global__ void __launch_bounds__(256)
softmax_kernel(const int* __restrict__ mask)
{
    __shared__ float qtab[8][64];
    __shared__ float bins[8][64];

    int tid  = threadIdx.x;
    int lane = tid & 31;
    int wid  = tid >> 5;

    int rowg = blockIdx.x * 8 + wid;      // bh*512 + q
    int bh = rowg >> 9;
    int q  = rowg & 511;
    int b  = bh >> 4;

    qtab[wid][lane]      = g_qrel[(size_t)rowg * NREL_ + lane];
    qtab[wid][lane + 32] = g_qrel[(size_t)rowg * NREL_ + lane + 32];
    bins[wid][lane]      = 0.f;
    bins[wid][lane + 32] = 0.f;
    __syncwarp();

    float4* srow = (float4*)(g_probs + (size_t)rowg * SS);
    const int4* mrow = (const int4*)(mask + ((size_t)b * SS + q) * SS);

    float s[16];
    float mx = -1e30f;
    #pragma unroll
    for (int i = 0; i < 4; i++) {
        float4 sc = srow[lane + 32 * i];
        int4   id = mrow[lane + 32 * i];
        float v0 = sc.x * 0.125f + qtab[wid][id.x] * 0.03125f + (id.x > 0 ? 0.f : -10000.f);
        float v1 = sc.y * 0.125f + qtab[wid][id.y] * 0.03125f + (id.y > 0 ? 0.f : -10000.f);
        float v2 = sc.z * 0.125f + qtab[wid][id.z] * 0.03125f + (id.z > 0 ? 0.f : -10000.f);
        float v3 = sc.w * 0.125f + qtab[wid][id.w] * 0.03125f + (id.w > 0 ? 0.f : -10000.f);
        s[i * 4 + 0] = v0; s[i * 4 + 1] = v1; s[i * 4 + 2] = v2; s[i * 4 + 3] = v3;
        mx = fmaxf(mx, fmaxf(fmaxf(v0, v1), fmaxf(v2, v3)));
    }
    #pragma unroll
    for (int o = 16; o; o >>= 1) mx = fmaxf(mx, __shfl_xor_sync(0xffffffffu, mx, o));

    float sum = 0.f;
    #pragma unroll
    for (int i = 0; i < 16; i++) {
        s[i] = __expf(s[i] - mx);
        sum += s[i];
    }
    #pragma unroll
    for (int o = 16; o; o >>= 1) sum += __shfl_xor_sync(0xffffffffu, sum, o);
    float inv = 1.f / sum;

    #pragma unroll
    for (int i = 0; i < 4; i++) {
        int4 id = mrow[lane + 32 * i];
        float p0 = s[i * 4 + 0] * inv;
        float p1 = s[i * 4 + 1] * inv;
        float p2 = s[i * 4 + 2] * inv;
        float p3 = s[i * 4 + 3] * inv;
        srow[lane + 32 * i] = make_float4(p0, p1, p2, p3);
        atomicAdd(&bins[wid][id.x], p0);
        atomicAdd(&bins[wid][id.y], p1);
        atomicAdd(&bins[wid][id.z], p2);
        atomicAdd(&bins[wid][id.w], p3);
    }
    __syncwarp();

    g_pr[(size_t)rowg * NREL_ + lane]      = bins[wid][lane];
    g_pr[(size_t)rowg * NREL_ + lane + 32] = bins[wid][lane + 32];
}

// ---------------- qrel = Q(BHS,64) @ rel_k_table(64,64)^T --------------------
__global__ void qrel_kernel(const float* __restrict__ relk)
{
    __shared__ float Qs[64][65];
    __shared__ float Rs[64][65];
    int tid = threadIdx.x;
    int row0 = blockIdx.x * 64;

    #pragma unroll
    for (int p = 0; p < 16; p++) {
        int idx = tid + p * 256;
        int d = idx & 63, r = idx >> 6;
        Qs[d][r] = g_Q[(size_t)(row0 + r) * 64 + d];
        Rs[d][r] = relk[r * 64 + d];
    }
    __syncthreads();

    int tx = tid & 15, ty = tid >> 4;
    float acc[4][4] = {};
    #pragma unroll
    for (int d = 0; d < 64; d++) {
        float a[4], b[4];
        #pragma unroll
        for (int i = 0; i < 4; i++) a[i] = Qs[d][ty * 4 + i];
        #pragma unroll
        for (int j = 0; j < 4; j++) b[j] = Rs[d][tx * 4 + j];
        #pragma unroll
        for (int i = 0; i < 4; i++)
            #pragma unroll
            for (int j = 0; j < 4; j++)
                acc[i][j] += a[i] * b[j];
    }
    #pragma unroll
    for (int i = 0; i < 4; i++)
        #pragma unroll
        for (int j = 0; j < 4; j++)
            g_qrel[(size_t)(row0 + ty * 4 + i) * NREL_ + tx * 4 + j] = acc[i][j];
}

// ---------------- out = probs @ V + 0.25 * pr @ rel_v_table ------------------
__global__ void av_kernel(const float* __restrict__ relv)
{
    __shared__ float Ps[64][65];
    __shared__ float Vs[64][68];
    int tid = threadIdx.x;
    int tx = tid & 15, ty = tid >> 4;
    int b = blockIdx.z, h = blockIdx.y;
    int bh = b * HH + h;
    int q0 = blockIdx.x * 64;

    float acc[4][4] = {};

    for (int kt = 0; kt < 9; kt++) {
        #pragma unroll
        for (int p = 0; p < 16; p++) {
            int idx = tid + p * 256;
            int c = idx & 63, r = idx >> 6;
            if (kt < 8) {
                Ps[r][c] = g_probs[((size_t)bh * SS + q0 + r) * SS + kt * 64 + c];
                Vs[r][c] = g_V   [((size_t)bh * SS + kt * 64 + r) * DD + c];
            } else {
                Ps[r][c] = 0.25f * g_pr[((size_t)bh * SS + q0 + r) * NREL_ + c];
                Vs[r][c] = relv[r * 64 + c];
            }
        }
        __syncthreads();
        #pragma unroll
        for (int kk = 0; kk < 64; kk++) {
            float4 b4 = *(const float4*)&Vs[kk][tx * 4];
            float bv[4] = {b4.x, b4.y, b4.z, b4.w};
            float av[4];
            #pragma unroll
            for (int i = 0; i < 4; i++) av[i] = Ps[ty * 4 + i][kk];
            #pragma unroll
            for (int i = 0; i < 4; i++)
                #pragma unroll
                for (int j = 0; j < 4; j++)
                    acc[i][j] += av[i] * bv[j];
        }
        __syncthreads();
    }

    #pragma unroll
    for (int i = 0; i < 4; i++) {
        int q = q0 + ty * 4 + i;
        #pragma unroll
        for (int j = 0; j < 4; j++) {
            int d = tx * 4 + j;
            g_attn[((size_t)b * SS + q) * HID_ + h * DD + d] =
                __uint_as_float(f2tf32(acc[i][j]));
        }
    }
}

// ---------------- launch -----------------------------------------------------
extern "C" void kernel_launch(void* const* d_in, const int* in_sizes, int n_in,
                              void* d_out, int out_size)
{
    const float* q_in = (const float*)d_in[0];
    const float* k_in = (const float*)d_in[1];
    const float* v_in = (const float*)d_in[2];
    const int*   mask = (const int*)  d_in[3];
    const float* Wq   = (const float*)d_in[4];
    const float* bq   = (const float*)d_in[5];
    const float* Wk   = (const float*)d_in[6];
    const float* bk   = (const float*)d_in[7];
    const float* Wv   = (const float*)d_in[8];
    const float* bv   = (const float*)d_in[9];
    const float* Wo   = (const float*)d_in[10];
    const float* bo   = (const float*)d_in[11];
    const float* relk = (const float*)d_in[12];
    const float* relv = (const float*)d_in[13];
    float* out = (float*)d_out;

    float *pQ, *pK, *pV, *pAttn;
    float *pRq, *pRk, *pRv, *pWq, *pWk, *pWv, *pWo;
    cudaGetSymbolAddress((void**)&pQ,    g_Q);
    cudaGetSymbolAddress((void**)&pK,    g_K);
    cudaGetSymbolAddress((void**)&pV,    g_V);
    cudaGetSymbolAddress((void**)&pAttn, g_attn);
    cudaGetSymbolAddress((void**)&pRq,   g_rq);
    cudaGetSymbolAddress((void**)&pRk,   g_rk);
    cudaGetSymbolAddress((void**)&pRv,   g_rv);
    cudaGetSymbolAddress((void**)&pWq,   g_wq);
    cudaGetSymbolAddress((void**)&pWk,   g_wk);
    cudaGetSymbolAddress((void**)&pWv,   g_wv);
    cudaGetSymbolAddress((void**)&pWo,   g_wo);

    // 1) tf32 pre-rounding of all GEMM inputs
    RoundArgs ra;
    ra.src[0] = (const float4*)q_in; ra.dst[0] = (float4*)pRq; ra.n4[0] = TT*HID_/4;
    ra.src[1] = (const float4*)k_in; ra.dst[1] = (float4*)pRk; ra.n4[1] = TT*HID_/4;
    ra.src[2] = (const float4*)v_in; ra.dst[2] = (float4*)pRv; ra.n4[2] = TT*HID_/4;
    ra.src[3] = (const float4*)Wq;   ra.dst[3] = (float4*)pWq; ra.n4[3] = HID_*HID_/4;
    ra.src[4] = (const float4*)Wk;   ra.dst[4] = (float4*)pWk; ra.n4[4] = HID_*HID_/4;
    ra.src[5] = (const float4*)Wv;   ra.dst[5] = (float4*)pWv; ra.n4[5] = HID_*HID_/4;
    ra.src[6] = (const float4*)Wo;   ra.dst[6] = (float4*)pWo; ra.n4[6] = HID_*HID_/4;
    round_tf32_kernel<<<dim3(512, 7), 256>>>(ra);

    const int gemmSmem = 2 * 2 * GTILE * 4;
    cudaFuncSetAttribute(tf32_gemm_kernel,
                         cudaFuncAttributeMaxDynamicSharedMemorySize, gemmSmem);

    // 2) fused QKV projection
    GemmArgs qkv;
    qkv.X[0] = pRq; qkv.X[1] = pRk; qkv.X[2] = pRv;
    qkv.W[0] = pWq; qkv.W[1] = pWk; qkv.W[2] = pWv;
    qkv.b[0] = bq;  qkv.b[1] = bk;  qkv.b[2] = bv;
    qkv.O[0] = pQ;  qkv.O[1] = pK;  qkv.O[2] = pV;
    qkv.scatter = 1;
    tf32_gemm_kernel<<<dim3(HID_ / GBN, TT / GBM, 3), 256, gemmSmem>>>(qkv);

    // 3) scores = Q @ K^T (tensor core)
    const int qkSmem = 2 * 128 * QKW * 4;
    cudaFuncSetAttribute(qk_scores_kernel,
                         cudaFuncAttributeMaxDynamicSharedMemorySize, qkSmem);
    qk_scores_kernel<<<dim3(4, 4, BH), 256, qkSmem>>>();

    qrel_kernel<<<BH * SS / 64, 256>>>(relk);

    // 4) softmax + relation bins (warp per row)
    softmax_kernel<<<BH * SS / 8, 256>>>(mask);

    // 5) AV + relation-V
    av_kernel<<<dim3(SS / 64, HH, BB), 256>>>(relv);

    // 6) output projection
    GemmArgs og;
    og.X[0] = pAttn; og.W[0] = pWo; og.b[0] = bo; og.O[0] = out;
    og.X[1] = og.X[2] = nullptr; og.W[1] = og.W[2] = nullptr;
    og.b[1] = og.b[2] = nullptr; og.O[1] = og.O[2] = nullptr;
    og.scatter = 0;
    tf32_gemm_kernel<<<dim3(HID_ / GBN, TT / GBM, 1), 256, gemmSmem>>>(og);
}

// round 5
// speedup vs baseline: 4.5467x; 2.0011x over previous
#include <cuda_runtime.h>
#include <cuda_bf16.h>
#include <math.h>
#include <stdint.h>

#define BB   4
#define SS   512
#define HID_ 1024
#define HH   16
#define DD   64
#define NREL_ 64
#define TT   (BB*SS)      // 2048 tokens
#define BH   (BB*HH)      // 64

// ---------------- scratch (static device globals; no allocations) ----------
__device__ float g_Q[BH*SS*DD];                // [bh][s][d], tf32-rounded
__device__ float g_K[BH*SS*DD];                // [bh][s][d], tf32-rounded
__device__ float g_V[BH*SS*DD];                // [bh][d][s]  (TRANSPOSED), rounded
__device__ float g_qrel[BH*SS*NREL_];          // fp32
__device__ float g_pr[BH*SS*NREL_];            // 0.25-scaled, tf32-rounded
__device__ float g_probs[(size_t)BH*SS*SS];    // scores -> probs(tf32) in place
__device__ float g_attn[(size_t)TT*HID_];      // tf32-rounded
// tf32-rounded copies of GEMM inputs + rel tables
__device__ float g_rq[TT*HID_];
__device__ float g_rk[TT*HID_];
__device__ float g_rv[TT*HID_];
__device__ float g_wq[HID_*HID_];
__device__ float g_wk[HID_*HID_];
__device__ float g_wv[HID_*HID_];
__device__ float g_wo[HID_*HID_];
__device__ float g_relk_r[NREL_*DD];
__device__ float g_relv_r[NREL_*DD];

__device__ __forceinline__ uint32_t f2tf32(float x) {
    uint32_t r;
    asm("cvt.rna.tf32.f32 %0, %1;" : "=r"(r) : "f"(x));
    return r;
}

// ---------------- tf32 pre-rounding pass ------------------------------------
struct RoundArgs {
    const float4* src[9];
    float4*       dst[9];
    int           n4[9];
};
__global__ void round_tf32_kernel(RoundArgs a)
{
    int seg = blockIdx.y;
    const float4* s = a.src[seg];
    float4*       d = a.dst[seg];
    int n = a.n4[seg];
    for (int i = blockIdx.x * blockDim.x + threadIdx.x; i < n;
         i += gridDim.x * blockDim.x) {
        float4 v = s[i];
        float4 o;
        o.x = __uint_as_float(f2tf32(v.x));
        o.y = __uint_as_float(f2tf32(v.y));
        o.z = __uint_as_float(f2tf32(v.z));
        o.w = __uint_as_float(f2tf32(v.w));
        d[i] = o;
    }
}

// ======================= MMA / cp.async helpers ==============================
__device__ __forceinline__ void mma_tf32(float c[4], const uint32_t a[4],
                                         const uint32_t b2[2]) {
    asm volatile(
        "mma.sync.aligned.m16n8k8.row.col.f32.tf32.tf32.f32 "
        "{%0,%1,%2,%3}, {%4,%5,%6,%7}, {%8,%9}, {%0,%1,%2,%3};"
        : "+f"(c[0]), "+f"(c[1]), "+f"(c[2]), "+f"(c[3])
        : "r"(a[0]), "r"(a[1]), "r"(a[2]), "r"(a[3]),
          "r"(b2[0]), "r"(b2[1]));
}
__device__ __forceinline__ void cp_async16(uint32_t smem, const void* g) {
    asm volatile("cp.async.cg.shared.global [%0], [%1], 16;\n"
                 :: "r"(smem), "l"(g));
}
__device__ __forceinline__ uint32_t smem_u32(const void* p) {
    return (uint32_t)__cvta_generic_to_shared(p);
}

// ======================= tf32 tensor-core GEMM (pipelined) ==================
// sc: 0 = row-major raw, 1 = scatter (B,H,S,D) rounded, 2 = scatter (B,H,D,S) rounded
struct GemmArgs {
    const float* X[3];
    const float* W[3];
    const float* b[3];
    float*       O[3];
    int sc[3];
};

#define GBM 128
#define GBN 128
#define GBK 32
#define GLDW 36
#define GTILE (GBM * GLDW)

__global__ void __launch_bounds__(256, 2)
tf32_gemm_kernel(GemmArgs args)
{
    const int K = 1024, N = 1024;
    int mat = blockIdx.z;
    const float* __restrict__ X    = args.X[mat];
    const float* __restrict__ W    = args.W[mat];
    const float* __restrict__ bias = args.b[mat];
    float* __restrict__ O          = args.O[mat];
    int sc = args.sc[mat];

    extern __shared__ uint32_t smg[];

    int tid  = threadIdx.x;
    int lane = tid & 31;
    int wid  = tid >> 5;
    int wm   = wid & 1;
    int wn   = wid >> 1;
    int gid  = lane >> 2;
    int tig  = lane & 3;

    int row0 = blockIdx.y * GBM;
    int col0 = blockIdx.x * GBN;

    int lr = tid >> 3;
    int lc = (tid & 7) * 4;

    uint32_t smem_base = smem_u32(smg);

    float acc[4][4][4] = {};
    const int KT = K / GBK;

    auto issue = [&](int st, int k0) {
        uint32_t xs = smem_base + (st * 2 * GTILE) * 4;
        uint32_t ws = xs + GTILE * 4;
        #pragma unroll
        for (int p = 0; p < 4; p++) {
            int r = lr + p * 32;
            cp_async16(xs + (r * GLDW + lc) * 4,
                       &X[(size_t)(row0 + r) * K + k0 + lc]);
            cp_async16(ws + (r * GLDW + lc) * 4,
                       &W[(size_t)(col0 + r) * K + k0 + lc]);
        }
    };

    issue(0, 0);
    asm volatile("cp.async.commit_group;\n" ::);

    for (int kt = 0; kt < KT; kt++) {
        if (kt + 1 < KT) {
            issue((kt + 1) & 1, (kt + 1) * GBK);
            asm volatile("cp.async.commit_group;\n" ::);
            asm volatile("cp.async.wait_group 1;\n" ::);
        } else {
            asm volatile("cp.async.wait_group 0;\n" ::);
        }
        __syncthreads();

        const uint32_t* Xs = smg + ((kt & 1) * 2) * GTILE;
        const uint32_t* Ws = Xs + GTILE;

        #pragma unroll
        for (int ks = 0; ks < 4; ks++) {
            int kb = ks * 8;
            uint32_t af[4][4];
            #pragma unroll
            for (int mt = 0; mt < 4; mt++) {
                int m = wm * 64 + mt * 16;
                af[mt][0] = Xs[(m + gid    ) * GLDW + kb + tig    ];
                af[mt][1] = Xs[(m + gid + 8) * GLDW + kb + tig    ];
                af[mt][2] = Xs[(m + gid    ) * GLDW + kb + tig + 4];
                af[mt][3] = Xs[(m + gid + 8) * GLDW + kb + tig + 4];
            }
            uint32_t bf[4][2];
            #pragma unroll
            for (int nt = 0; nt < 4; nt++) {
                int n = wn * 32 + nt * 8;
                bf[nt][0] = Ws[(n + gid) * GLDW + kb + tig    ];
                bf[nt][1] = Ws[(n + gid) * GLDW + kb + tig + 4];
            }
            #pragma unroll
            for (int mt = 0; mt < 4; mt++)
                #pragma unroll
                for (int nt = 0; nt < 4; nt++)
                    mma_tf32(acc[mt][nt], af[mt], bf[nt]);
        }
        __syncthreads();
    }

    #pragma unroll
    for (int mt = 0; mt < 4; mt++) {
        #pragma unroll
        for (int nt = 0; nt < 4; nt++) {
            #pragma unroll
            for (int c = 0; c < 4; c++) {
                int m = row0 + wm * 64 + mt * 16 + gid + (c >= 2 ? 8 : 0);
                int n = col0 + wn * 32 + nt * 8 + tig * 2 + (c & 1);
                float y = acc[mt][nt][c] + bias[n];
                if (sc == 1) {
                    int b = m >> 9, s = m & 511, h = n >> 6, d = n & 63;
                    O[(((size_t)b * HH + h) * SS + s) * DD + d] =
                        __uint_as_float(f2tf32(y));
                } else if (sc == 2) {
                    int b = m >> 9, s = m & 511, h = n >> 6, d = n & 63;
                    O[(((size_t)b * HH + h) * DD + d) * SS + s] =
                        __uint_as_float(f2tf32(y));
                } else {
                    O[(size_t)m * N + n] = y;
                }
            }
        }
    }
}

// ================= qk_scores (+fused qrel): tf32 MMA =========================
// grid (4 ntiles, 4 mtiles, 64 bh), 256 threads, 128x128 tile, K=64.
// blocks with ntile==0 additionally compute qrel = Q @ rel_k^T for their rows.
#define QKW 68

__global__ void __launch_bounds__(256, 2)
qk_scores_kernel()
{
    extern __shared__ uint32_t sm2[];   // Qs[128][68] Ks[128][68] Rs[64][68]
    uint32_t* Qs = sm2;
    uint32_t* Ks = sm2 + 128 * QKW;
    uint32_t* Rs = sm2 + 256 * QKW;

    int tid  = threadIdx.x;
    int lane = tid & 31;
    int wid  = tid >> 5;
    int wm   = wid & 1;
    int wn   = wid >> 1;
    int gid  = lane >> 2;
    int tig  = lane & 3;

    int bh   = blockIdx.z;
    int row0 = blockIdx.y * 128;
    int col0 = blockIdx.x * 128;

    const float* Qg = g_Q + (size_t)bh * SS * DD;
    const float* Kg = g_K + (size_t)bh * SS * DD;

    uint32_t qs0 = smem_u32(Qs);
    uint32_t ks0 = smem_u32(Ks);
    uint32_t rs0 = smem_u32(Rs);

    // cp.async the tiles (Q/K pre-rounded by projection epilogue)
    #pragma unroll
    for (int p = 0; p < 8; p++) {
        int ch = tid + p * 256;           // 0..2047
        int r = ch >> 4, c4 = (ch & 15) * 4;
        cp_async16(qs0 + (r * QKW + c4) * 4, &Qg[(size_t)(row0 + r) * DD + c4]);
        cp_async16(ks0 + (r * QKW + c4) * 4, &Kg[(size_t)(col0 + r) * DD + c4]);
    }
    if (col0 == 0) {
        #pragma unroll
        for (int p = 0; p < 4; p++) {
            int ch = tid + p * 256;       // 0..1023
            int r = ch >> 4, c4 = (ch & 15) * 4;
            cp_async16(rs0 + (r * QKW + c4) * 4, &g_relk_r[r * DD + c4]);
        }
    }
    asm volatile("cp.async.commit_group;\n" ::);
    asm volatile("cp.async.wait_group 0;\n" ::);
    __syncthreads();

    // fused qrel (only first n-tile; warps wn<2 cover the 64 rel columns)
    if (col0 == 0 && wn < 2) {
        float acc2[4][4][4] = {};
        #pragma unroll
        for (int ks = 0; ks < 8; ks++) {
            int kb = ks * 8;
            uint32_t af[4][4];
            #pragma unroll
            for (int mt = 0; mt < 4; mt++) {
                int m = wm * 64 + mt * 16;
                af[mt][0] = Qs[(m + gid    ) * QKW + kb + tig    ];
                af[mt][1] = Qs[(m + gid + 8) * QKW + kb + tig    ];
                af[mt][2] = Qs[(m + gid    ) * QKW + kb + tig + 4];
                af[mt][3] = Qs[(m + gid + 8) * QKW + kb + tig + 4];
            }
            uint32_t bf[4][2];
            #pragma unroll
            for (int nt = 0; nt < 4; nt++) {
                int n = wn * 32 + nt * 8;
                bf[nt][0] = Rs[(n + gid) * QKW + kb + tig    ];
                bf[nt][1] = Rs[(n + gid) * QKW + kb + tig + 4];
            }
            #pragma unroll
            for (int mt = 0; mt < 4; mt++)
                #pragma unroll
                for (int nt = 0; nt < 4; nt++)
                    mma_tf32(acc2[mt][nt], af[mt], bf[nt]);
        }
        #pragma unroll
        for (int mt = 0; mt < 4; mt++) {
            #pragma unroll
            for (int nt = 0; nt < 4; nt++) {
                int m0 = row0 + wm * 64 + mt * 16 + gid;
                int n  = wn * 32 + nt * 8 + tig * 2;
                *(float2*)&g_qrel[((size_t)bh * SS + m0) * NREL_ + n] =
                    make_float2(acc2[mt][nt][0], acc2[mt][nt][1]);
                *(float2*)&g_qrel[((size_t)bh * SS + m0 + 8) * NREL_ + n] =
                    make_float2(acc2[mt][nt][2], acc2[mt][nt][3]);
            }
        }
    }

    float acc[4][4][4] = {};
    #pragma unroll
    for (int ks = 0; ks < 8; ks++) {
        int kb = ks * 8;
        uint32_t af[4][4];
        #pragma unroll
        for (int mt = 0; mt < 4; mt++) {
            int m = wm * 64 + mt * 16;
            af[mt][0] = Qs[(m + gid    ) * QKW + kb + tig    ];
            af[mt][1] = Qs[(m + gid + 8) * QKW + kb + tig    ];
            af[mt][2] = Qs[(m + gid    ) * QKW + kb + tig + 4];
            af[mt][3] = Qs[(m + gid + 8) * QKW + kb + tig + 4];
        }
        uint32_t bf[4][2];
        #pragma unroll
        for (int nt = 0; nt < 4; nt++) {
            int n = wn * 32 + nt * 8;
            bf[nt][0] = Ks[(n + gid) * QKW + kb + tig    ];
            bf[nt][1] = Ks[(n + gid) * QKW + kb + tig + 4];
        }
        #pragma unroll
        for (int mt = 0; mt < 4; mt++)
            #pragma unroll
            for (int nt = 0; nt < 4; nt++)
                mma_tf32(acc[mt][nt], af[mt], bf[nt]);
    }

    float* Og = g_probs + (size_t)bh * SS * SS;
    #pragma unroll
    for (int mt = 0; mt < 4; mt++) {
        #pragma unroll
        for (int nt = 0; nt < 4; nt++) {
            int m0 = row0 + wm * 64 + mt * 16 + gid;
            int n  = col0 + wn * 32 + nt * 8 + tig * 2;
            *(float2*)&Og[(size_t)m0 * SS + n] =
                make_float2(acc[mt][nt][0], acc[mt][nt][1]);
            *(float2*)&Og[(size_t)(m0 + 8) * SS + n] =
                make_float2(acc[mt][nt][2], acc[mt][nt][3]);
        }
    }
}

// ================= softmax: warp per row, no block barriers ==================
__global__ void __launch_bounds__(256)
softmax_kernel(const int* __restrict__ mask)
{
    __shared__ float qtab[8][64];
    __shared__ float bins[8][64];

    int tid  = threadIdx.x;
    int lane = tid & 31;
    int wid  = tid >> 5;

    int rowg = blockIdx.x * 8 + wid;      // bh*512 + q
    int bh = rowg >> 9;
    int q  = rowg & 511;
    int b  = bh >> 4;

    qtab[wid][lane]      = g_qrel[(size_t)rowg * NREL_ + lane];
    qtab[wid][lane + 32] = g_qrel[(size_t)rowg * NREL_ + lane + 32];
    bins[wid][lane]      = 0.f;
    bins[wid][lane + 32] = 0.f;
    __syncwarp();

    float4* srow = (float4*)(g_probs + (size_t)rowg * SS);
    const int4* mrow = (const int4*)(mask + ((size_t)b * SS + q) * SS);

    float s[16];
    float mx = -1e30f;
    #pragma unroll
    for (int i = 0; i < 4; i++) {
        float4 sc = srow[lane + 32 * i];
        int4   id = mrow[lane + 32 * i];
        float v0 = sc.x * 0.125f + qtab[wid][id.x] * 0.03125f + (id.x > 0 ? 0.f : -10000.f);
        float v1 = sc.y * 0.125f + qtab[wid][id.y] * 0.03125f + (id.y > 0 ? 0.f : -10000.f);
        float v2 = sc.z * 0.125f + qtab[wid][id.z] * 0.03125f + (id.z > 0 ? 0.f : -10000.f);
        float v3 = sc.w * 0.125f + qtab[wid][id.w] * 0.03125f + (id.w > 0 ? 0.f : -10000.f);
        s[i * 4 + 0] = v0; s[i * 4 + 1] = v1; s[i * 4 + 2] = v2; s[i * 4 + 3] = v3;
        mx = fmaxf(mx, fmaxf(fmaxf(v0, v1), fmaxf(v2, v3)));
    }
    #pragma unroll
    for (int o = 16; o; o >>= 1) mx = fmaxf(mx, __shfl_xor_sync(0xffffffffu, mx, o));

    float sum = 0.f;
    #pragma unroll
    for (int i = 0; i < 16; i++) {
        s[i] = __expf(s[i] - mx);
        sum += s[i];
    }
    #pragma unroll
    for (int o = 16; o; o >>= 1) sum += __shfl_xor_sync(0xffffffffu, sum, o);
    float inv = 1.f / sum;

    #pragma unroll
    for (int i = 0; i < 4; i++) {
        int4 id = mrow[lane + 32 * i];
        float p0 = s[i * 4 + 0] * inv;
        float p1 = s[i * 4 + 1] * inv;
        float p2 = s[i * 4 + 2] * inv;
        float p3 = s[i * 4 + 3] * inv;
        srow[lane + 32 * i] = make_float4(
            __uint_as_float(f2tf32(p0)), __uint_as_float(f2tf32(p1)),
            __uint_as_float(f2tf32(p2)), __uint_as_float(f2tf32(p3)));
        atomicAdd(&bins[wid][id.x], p0);
        atomicAdd(&bins[wid][id.y], p1);
        atomicAdd(&bins[wid][id.z], p2);
        atomicAdd(&bins[wid][id.w], p3);
    }
    __syncwarp();

    g_pr[(size_t)rowg * NREL_ + lane] =
        __uint_as_float(f2tf32(0.25f * bins[wid][lane]));
    g_pr[(size_t)rowg * NREL_ + lane + 32] =
        __uint_as_float(f2tf32(0.25f * bins[wid][lane + 32]));
}

// ================= av: out = probs @ V + pr' @ rel_v (tf32 MMA) ==============
// grid (4 q-tiles, 64 bh), 256 threads; 128x64 output tile; 9 k-tiles of 64.
#define AVW 68
#define AVPT (128 * AVW)     // P tile words per stage
#define AVVT (64 * AVW)      // V tile words per stage
#define AVST (AVPT + AVVT)

__global__ void __launch_bounds__(256)
av_kernel()
{
    extern __shared__ uint32_t sm3[];   // [2][Ps 128x68 | Vs 64x68]

    int tid  = threadIdx.x;
    int lane = tid & 31;
    int wid  = tid >> 5;
    int wm   = wid & 1;        // 2 warps over 128 rows
    int wn   = wid >> 1;       // 4 warps over 64 cols (16 each)
    int gid  = lane >> 2;
    int tig  = lane & 3;

    int bh = blockIdx.y;
    int q0 = blockIdx.x * 128;
    int b  = bh >> 4, h = bh & 15;

    uint32_t smem_base = smem_u32(sm3);

    const float* Pg  = g_probs + (size_t)bh * SS * SS;
    const float* PRg = g_pr + ((size_t)bh * SS + q0) * NREL_;
    const float* Vg  = g_V + (size_t)bh * SS * DD;   // [d][s]

    auto issue = [&](int st, int kt) {
        uint32_t ps = smem_base + (st * AVST) * 4;
        uint32_t vs = ps + AVPT * 4;
        if (kt < 8) {
            #pragma unroll
            for (int p = 0; p < 8; p++) {
                int ch = tid + p * 256;        // 0..2047
                int r = ch >> 4, c4 = (ch & 15) * 4;
                cp_async16(ps + (r * AVW + c4) * 4,
                           &Pg[(size_t)(q0 + r) * SS + kt * 64 + c4]);
            }
            #pragma unroll
            for (int p = 0; p < 4; p++) {
                int ch = tid + p * 256;        // 0..1023
                int r = ch >> 4, c4 = (ch & 15) * 4;
                cp_async16(vs + (r * AVW + c4) * 4,
                           &Vg[(size_t)r * SS + kt * 64 + c4]);
            }
        } else {
            #pragma unroll
            for (int p = 0; p < 8; p++) {
                int ch = tid + p * 256;
                int r = ch >> 4, c4 = (ch & 15) * 4;
                cp_async16(ps + (r * AVW + c4) * 4, &PRg[(size_t)r * NREL_ + c4]);
            }
            // rel_v transposed: Vs[d][r] = relv[r][d]
            uint32_t* vsp = sm3 + st * AVST + AVPT;
            #pragma unroll
            for (int p = 0; p < 16; p++) {
                int idx = tid + p * 256;       // 0..4095
                int d = idx & 63, r = idx >> 6;
                vsp[d * AVW + r] = __float_as_uint(g_relv_r[r * DD + d]);
            }
        }
    };

    float acc[4][4] = {};   // [mt][c], per nt handled below via acc2
    float acc2[4][4] = {};  // second n-tile

    issue(0, 0);
    asm volatile("cp.async.commit_group;\n" ::);

    for (int kt = 0; kt < 9; kt++) {
        if (kt + 1 < 9) {
            issue((kt + 1) & 1, kt + 1);
            asm volatile("cp.async.commit_group;\n" ::);
            asm volatile("cp.async.wait_group 1;\n" ::);
        } else {
            asm volatile("cp.async.wait_group 0;\n" ::);
        }
        __syncthreads();

        const uint32_t* Ps = sm3 + (kt & 1) * AVST;
        const uint32_t* Vs = Ps + AVPT;

        #pragma unroll
        for (int ks = 0; ks < 8; ks++) {
            int kb = ks * 8;
            uint32_t af[4][4];
            #pragma unroll
            for (int mt = 0; mt < 4; mt++) {
                int m = wm * 64 + mt * 16;
                af[mt][0] = Ps[(m + gid    ) * AVW + kb + tig    ];
                af[mt][1] = Ps[(m + gid + 8) * AVW + kb + tig    ];
                af[mt][2] = Ps[(m + gid    ) * AVW + kb + tig + 4];
                af[mt][3] = Ps[(m + gid + 8) * AVW + kb + tig + 4];
            }
            uint32_t bf0[2], bf1[2];
            int n0 = wn * 16;
            bf0[0] = Vs[(n0 + gid    ) * AVW + kb + tig    ];
            bf0[1] = Vs[(n0 + gid    ) * AVW + kb + tig + 4];
            bf1[0] = Vs[(n0 + 8 + gid) * AVW + kb + tig    ];
            bf1[1] = Vs[(n0 + 8 + gid) * AVW + kb + tig + 4];
            #pragma unroll
            for (int mt = 0; mt < 4; mt++) {
                mma_tf32(acc[mt],  af[mt], bf0);
                mma_tf32(acc2[mt], af[mt], bf1);
            }
        }
        __syncthreads();
    }

    #pragma unroll
    for (int mt = 0; mt < 4; mt++) {
        #pragma unroll
        for (int c = 0; c < 4; c++) {
            int q = q0 + wm * 64 + mt * 16 + gid + (c >= 2 ? 8 : 0);
            int n0 = wn * 16 + tig * 2 + (c & 1);
            g_attn[((size_t)b * SS + q) * HID_ + h * DD + n0] =
                __uint_as_float(f2tf32(acc[mt][c]));
            g_attn[((size_t)b * SS + q) * HID_ + h * DD + n0 + 8] =
                __uint_as_float(f2tf32(acc2[mt][c]));
        }
    }
}

// ---------------- launch -----------------------------------------------------
extern "C" void kernel_launch(void* const* d_in, const int* in_sizes, int n_in,
                              void* d_out, int out_size)
{
    const float* q_in = (const float*)d_in[0];
    const float* k_in = (const float*)d_in[1];
    const float* v_in = (const float*)d_in[2];
    const int*   mask = (const int*)  d_in[3];
    const float* Wq   = (const float*)d_in[4];
    const float* bq   = (const float*)d_in[5];
    const float* Wk   = (const float*)d_in[6];
    const float* bk   = (const float*)d_in[7];
    const float* Wv   = (const float*)d_in[8];
    const float* bv   = (const float*)d_in[9];
    const float* Wo   = (const float*)d_in[10];
    const float* bo   = (const float*)d_in[11];
    const float* relk = (const float*)d_in[12];
    const float* relv = (const float*)d_in[13];
    float* out = (float*)d_out;

    float *pQ, *pK, *pV, *pAttn;
    float *pRq, *pRk, *pRv, *pWq, *pWk, *pWv, *pWo, *pRelk, *pRelv;
    cudaGetSymbolAddress((void**)&pQ,    g_Q);
    cudaGetSymbolAddress((void**)&pK,    g_K);
    cudaGetSymbolAddress((void**)&pV,    g_V);
    cudaGetSymbolAddress((void**)&pAttn, g_attn);
    cudaGetSymbolAddress((void**)&pRq,   g_rq);
    cudaGetSymbolAddress((void**)&pRk,   g_rk);
    cudaGetSymbolAddress((void**)&pRv,   g_rv);
    cudaGetSymbolAddress((void**)&pWq,   g_wq);
    cudaGetSymbolAddress((void**)&pWk,   g_wk);
    cudaGetSymbolAddress((void**)&pWv,   g_wv);
    cudaGetSymbolAddress((void**)&pWo,   g_wo);
    cudaGetSymbolAddress((void**)&pRelk, g_relk_r);
    cudaGetSymbolAddress((void**)&pRelv, g_relv_r);

    // 1) tf32 pre-rounding
    RoundArgs ra;
    ra.src[0] = (const float4*)q_in; ra.dst[0] = (float4*)pRq; ra.n4[0] = TT*HID_/4;
    ra.src[1] = (const float4*)k_in; ra.dst[1] = (float4*)pRk; ra.n4[1] = TT*HID_/4;
    ra.src[2] = (const float4*)v_in; ra.dst[2] = (float4*)pRv; ra.n4[2] = TT*HID_/4;
    ra.src[3] = (const float4*)Wq;   ra.dst[3] = (float4*)pWq; ra.n4[3] = HID_*HID_/4;
    ra.src[4] = (const float4*)Wk;   ra.dst[4] = (float4*)pWk; ra.n4[4] = HID_*HID_/4;
    ra.src[5] = (const float4*)Wv;   ra.dst[5] = (float4*)pWv; ra.n4[5] = HID_*HID_/4;
    ra.src[6] = (const float4*)Wo;   ra.dst[6] = (float4*)pWo; ra.n4[6] = HID_*HID_/4;
    ra.src[7] = (const float4*)relk; ra.dst[7] = (float4*)pRelk; ra.n4[7] = NREL_*DD/4;
    ra.src[8] = (const float4*)relv; ra.dst[8] = (float4*)pRelv; ra.n4[8] = NREL_*DD/4;
    round_tf32_kernel<<<dim3(512, 9), 256>>>(ra);

    const int gemmSmem = 2 * 2 * GTILE * 4;
    cudaFuncSetAttribute(tf32_gemm_kernel,
                         cudaFuncAttributeMaxDynamicSharedMemorySize, gemmSmem);

    // 2) fused QKV projection (V stored transposed per head)
    GemmArgs qkv;
    qkv.X[0] = pRq; qkv.X[1] = pRk; qkv.X[2] = pRv;
    qkv.W[0] = pWq; qkv.W[1] = pWk; qkv.W[2] = pWv;
    qkv.b[0] = bq;  qkv.b[1] = bk;  qkv.b[2] = bv;
    qkv.O[0] = pQ;  qkv.O[1] = pK;  qkv.O[2] = pV;
    qkv.sc[0] = 1;  qkv.sc[1] = 1;  qkv.sc[2] = 2;
    tf32_gemm_kernel<<<dim3(HID_ / GBN, TT / GBM, 3), 256, gemmSmem>>>(qkv);

    // 3) scores = Q @ K^T (+ fused qrel)
    const int qkSmem = (256 * QKW + 64 * QKW) * 4;
    cudaFuncSetAttribute(qk_scores_kernel,
                         cudaFuncAttributeMaxDynamicSharedMemorySize, qkSmem);
    qk_scores_kernel<<<dim3(4, 4, BH), 256, qkSmem>>>();

    // 4) softmax + relation bins
    softmax_kernel<<<BH * SS / 8, 256>>>(mask);

    // 5) AV + relation-V (tensor core)
    const int avSmem = 2 * AVST * 4;
    cudaFuncSetAttribute(av_kernel,
                         cudaFuncAttributeMaxDynamicSharedMemorySize, avSmem);
    av_kernel<<<dim3(4, BH), 256, avSmem>>>();

    // 6) output projection
    GemmArgs og;
    og.X[0] = pAttn; og.W[0] = pWo; og.b[0] = bo; og.O[0] = out;
    og.X[1] = og.X[2] = nullptr; og.W[1] = og.W[2] = nullptr;
    og.b[1] = og.b[2] = nullptr; og.O[1] = og.O[2] = nullptr;
    og.sc[0] = 0; og.sc[1] = 0; og.sc[2] = 0;
    tf32_gemm_kernel<<<dim3(HID_ / GBN, TT / GBM, 1), 256, gemmSmem>>>(og);
}